// round 6
// baseline (speedup 1.0000x reference)
#include <cuda_runtime.h>
#include <cuda_bf16.h>
#include <math.h>
#include <stdint.h>

// Shapes (fixed)
#define R_TOTAL 4096
#define DQ      512
#define DC      256
#define MTOK    64
#define NHEADS  8
#define DHEAD   64
#define INNER   512

// Scratch (no allocs allowed)
__device__ float g_Q   [R_TOTAL * INNER];
__device__ float g_Qk  [R_TOTAL * NHEADS * DC];
__device__ float g_ctxA[R_TOTAL * NHEADS * DC];
__device__ float g_O1  [R_TOTAL * INNER];
__device__ float g_WqT [INNER * DQ];
__device__ float g_WoT [DQ * INNER];
__device__ float g_WvT [INNER * DC];

// ---------------- helpers ----------------
__device__ __forceinline__ uint32_t smem_u32(const void* p) {
    uint32_t a;
    asm("{ .reg .u64 t; cvta.to.shared.u64 t, %1; cvt.u32.u64 %0, t; }"
        : "=r"(a) : "l"(p));
    return a;
}
__device__ __forceinline__ void ldm_x4(uint32_t* r, uint32_t addr) {
    asm volatile("ldmatrix.sync.aligned.m8n8.x4.shared.b16 {%0,%1,%2,%3}, [%4];"
                 : "=r"(r[0]), "=r"(r[1]), "=r"(r[2]), "=r"(r[3]) : "r"(addr));
}
__device__ __forceinline__ void ldm_x2(uint32_t* r, uint32_t addr) {
    asm volatile("ldmatrix.sync.aligned.m8n8.x2.shared.b16 {%0,%1}, [%2];"
                 : "=r"(r[0]), "=r"(r[1]) : "r"(addr));
}
__device__ __forceinline__ void ldm_x4_t(uint32_t* r, uint32_t addr) {
    asm volatile("ldmatrix.sync.aligned.m8n8.x4.trans.shared.b16 {%0,%1,%2,%3}, [%4];"
                 : "=r"(r[0]), "=r"(r[1]), "=r"(r[2]), "=r"(r[3]) : "r"(addr));
}
__device__ __forceinline__ void ldm_x2_t(uint32_t* r, uint32_t addr) {
    asm volatile("ldmatrix.sync.aligned.m8n8.x2.trans.shared.b16 {%0,%1}, [%2];"
                 : "=r"(r[0]), "=r"(r[1]) : "r"(addr));
}
__device__ __forceinline__ void mma_bf16(float* c, const uint32_t* a, const uint32_t* b) {
    asm volatile("mma.sync.aligned.m16n8k16.row.col.f32.bf16.bf16.f32 "
                 "{%0,%1,%2,%3}, {%4,%5,%6,%7}, {%8,%9}, {%0,%1,%2,%3};"
                 : "+f"(c[0]), "+f"(c[1]), "+f"(c[2]), "+f"(c[3])
                 : "r"(a[0]), "r"(a[1]), "r"(a[2]), "r"(a[3]), "r"(b[0]), "r"(b[1]));
}
__device__ __forceinline__ uint32_t pack2(__nv_bfloat16 a, __nv_bfloat16 b) {
    uint16_t ua = *(uint16_t*)&a, ub = *(uint16_t*)&b;
    return (uint32_t)ua | ((uint32_t)ub << 16);
}
__device__ __forceinline__ void split_pack(float4 v, uint2& hi, uint2& lo) {
    __nv_bfloat16 hx = __float2bfloat16_rn(v.x);
    __nv_bfloat16 hy = __float2bfloat16_rn(v.y);
    __nv_bfloat16 hz = __float2bfloat16_rn(v.z);
    __nv_bfloat16 hw = __float2bfloat16_rn(v.w);
    __nv_bfloat16 lx = __float2bfloat16_rn(v.x - __bfloat162float(hx));
    __nv_bfloat16 ly = __float2bfloat16_rn(v.y - __bfloat162float(hy));
    __nv_bfloat16 lz = __float2bfloat16_rn(v.z - __bfloat162float(hz));
    __nv_bfloat16 lw = __float2bfloat16_rn(v.w - __bfloat162float(hw));
    hi = make_uint2(pack2(hx, hy), pack2(hz, hw));
    lo = make_uint2(pack2(lx, ly), pack2(lz, lw));
}
__device__ __forceinline__ void cp16(uint32_t dst, const void* src) {
    asm volatile("cp.async.cg.shared.global [%0], [%1], 16;"
                 :: "r"(dst), "l"(src) : "memory");
}
#define CP_COMMIT() asm volatile("cp.async.commit_group;" ::: "memory")
#define CP_WAIT0()  asm volatile("cp.async.wait_group 0;" ::: "memory")

// ---------------------------------------------------------------------------
// bf16 3-term mma.sync GEMM (unchanged, proven)
// ---------------------------------------------------------------------------
#define LROW 40
#define LROWB 80

template<int BN, int MW, int NW, bool BIAS>
__global__ __launch_bounds__(256, 1)
void hgemm(const float* __restrict__ A, int lda, long long bsA,
           const float* __restrict__ B, int ldb, long long bsB,
           float* __restrict__ C, int ldc, long long bsC,
           const float* __restrict__ bias, int K)
{
    constexpr int WM = 128 / MW;
    constexpr int WN = BN / NW;
    constexpr int MT = WM / 16;
    constexpr int NT = WN / 8;
    constexpr int A_BYTES = 128 * LROWB;
    constexpr int B_BYTES = BN * LROWB;
    constexpr int STAGE = 2 * A_BYTES + 2 * B_BYTES;

    extern __shared__ char smc[];
    const uint32_t smb = smem_u32(smc);

    const int t = threadIdx.x;
    const int wid = t >> 5, lane = t & 31;
    const int wr = wid / NW, wc = wid % NW;
    const int wm = wr * WM, wn = wc * WN;
    const int bm = blockIdx.y * 128, bn = blockIdx.x * BN;

    A += (long long)blockIdx.z * bsA;
    B += (long long)blockIdx.z * bsB;
    C += (long long)blockIdx.z * bsC;

    const int rloc = t >> 3;
    const int f4   = t & 7;

    float acc[MT][NT][4];
#pragma unroll
    for (int i = 0; i < MT; i++)
#pragma unroll
        for (int j = 0; j < NT; j++)
#pragma unroll
            for (int q = 0; q < 4; q++) acc[i][j][q] = 0.0f;

    const int ns = K >> 5;
    float4 pa[4], pb[BN / 32];

    const uint32_t a_off = (uint32_t)(((wm + (lane & 15)) * LROW + (lane >> 4) * 8) * 2);
    const uint32_t b_off = (uint32_t)(((wn + (lane & 7)) * LROW + ((lane >> 3) & 1) * 8) * 2);

    auto gload = [&](int s) {
#pragma unroll
        for (int i = 0; i < 4; i++)
            pa[i] = *(const float4*)(A + (long long)(bm + rloc + i * 32) * lda + s * 32 + f4 * 4);
#pragma unroll
        for (int i = 0; i < BN / 32; i++)
            pb[i] = *(const float4*)(B + (long long)(bn + rloc + i * 32) * ldb + s * 32 + f4 * 4);
    };
    auto sstore = [&](int buf) {
        char* base = smc + buf * STAGE;
#pragma unroll
        for (int i = 0; i < 4; i++) {
            uint2 hi, lo; split_pack(pa[i], hi, lo);
            int r = rloc + i * 32;
            *(uint2*)(base + r * LROWB + f4 * 8)           = hi;
            *(uint2*)(base + A_BYTES + r * LROWB + f4 * 8) = lo;
        }
        char* bb = base + 2 * A_BYTES;
#pragma unroll
        for (int i = 0; i < BN / 32; i++) {
            uint2 hi, lo; split_pack(pb[i], hi, lo);
            int r = rloc + i * 32;
            *(uint2*)(bb + r * LROWB + f4 * 8)           = hi;
            *(uint2*)(bb + B_BYTES + r * LROWB + f4 * 8) = lo;
        }
    };
    auto compute = [&](int buf) {
        const uint32_t sa = smb + buf * STAGE;
        const uint32_t sb = sa + 2 * A_BYTES;
#pragma unroll
        for (int ks = 0; ks < 2; ks++) {
            uint32_t afh[MT][4], afl[MT][4], bfh[NT][2], bfl[NT][2];
#pragma unroll
            for (int mt = 0; mt < MT; mt++) {
                uint32_t ad = sa + a_off + mt * (16 * LROWB) + ks * 32;
                ldm_x4(afh[mt], ad);
                ldm_x4(afl[mt], ad + A_BYTES);
            }
#pragma unroll
            for (int nt = 0; nt < NT; nt++) {
                uint32_t bd = sb + b_off + nt * (8 * LROWB) + ks * 32;
                ldm_x2(bfh[nt], bd);
                ldm_x2(bfl[nt], bd + B_BYTES);
            }
#pragma unroll
            for (int mt = 0; mt < MT; mt++)
#pragma unroll
                for (int nt = 0; nt < NT; nt++) {
                    mma_bf16(acc[mt][nt], afh[mt], bfh[nt]);
                    mma_bf16(acc[mt][nt], afh[mt], bfl[nt]);
                    mma_bf16(acc[mt][nt], afl[mt], bfh[nt]);
                }
        }
    };

    gload(0);
    sstore(0);
    __syncthreads();
    for (int s = 0; s < ns; s++) {
        if (s + 1 < ns) gload(s + 1);
        compute(s & 1);
        if (s + 1 < ns) {
            sstore((s + 1) & 1);
            __syncthreads();
        }
    }

    const int g = lane >> 2, tq = lane & 3;
#pragma unroll
    for (int mt = 0; mt < MT; mt++) {
        int r0 = bm + wm + mt * 16 + g;
#pragma unroll
        for (int nt = 0; nt < NT; nt++) {
            int col = bn + wn + nt * 8 + tq * 2;
            float b0 = 0.f, b1 = 0.f;
            if (BIAS) { b0 = bias[col]; b1 = bias[col + 1]; }
            *(float2*)(C + (long long)r0 * ldc + col) =
                make_float2(acc[mt][nt][0] + b0, acc[mt][nt][1] + b1);
            *(float2*)(C + (long long)(r0 + 8) * ldc + col) =
                make_float2(acc[mt][nt][2] + b0, acc[mt][nt][3] + b1);
        }
    }
}

// ---------------------------------------------------------------------------
// Weight transpose
// ---------------------------------------------------------------------------
__global__ void transpose_k(const float* __restrict__ src, float* __restrict__ dst,
                            int R, int C)
{
    __shared__ float tile[32][33];
    int bx = blockIdx.x * 32, by = blockIdx.y * 32;
#pragma unroll
    for (int j = 0; j < 32; j += 8)
        tile[threadIdx.y + j][threadIdx.x] =
            src[(long long)(by + threadIdx.y + j) * C + bx + threadIdx.x];
    __syncthreads();
#pragma unroll
    for (int j = 0; j < 32; j += 8)
        dst[(long long)(bx + threadIdx.y + j) * R + by + threadIdx.x] =
            tile[threadIdx.x][threadIdx.y + j];
}

// ---------------------------------------------------------------------------
// Streaming tensor-core attention core. One CTA handles AC_G rows, cp.async
// pipeline: stage row i+1 (fp32) while MMA phases of row i run.
// ---------------------------------------------------------------------------
#define AC_G 8
#define AC_LDC 528
// smem byte offsets
#define ST_CTX 0          // 65536  fp32 ctx staging (64 x 1024B)
#define ST_QK  65536      // 8192   fp32 qk staging
#define ST_BI  73728      // 256
#define ST_MK  73984      // 256
#define AC_CH  74240      // 33792  ctx hi bf16 (64 x 528B)
#define AC_CL  108032     // 33792  ctx lo
#define AC_QH  141824     // 4224   qk hi (8 x 528B)
#define AC_QL  146048     // 4224   qk lo
#define AC_AH  150272     // 3072   attn^T hi (64 x 48B)
#define AC_AL  153344     // 3072   attn^T lo
#define AC_SA  156416     // 2304   partial scores (64 x 9 f32)
#define AC_SB  158720     // 2304
#define AC_WB  161024     // 256    bias (work copy)
#define AC_WM  161280     // 256    mask (work copy)
#define AC_BYTES 161536

__global__ __launch_bounds__(256)
void attn_core(const float* __restrict__ ctx,
               const int* __restrict__ mask,
               const float* __restrict__ bias)
{
    extern __shared__ char sm[];
    const uint32_t smb = smem_u32(sm);
    const int t = threadIdx.x;
    const int wid = t >> 5, lane = t & 31;
    const int r0 = blockIdx.x * AC_G;

    auto issue_stage = [&](int r) {
        const char* gctx = (const char*)(ctx + (size_t)r * (MTOK * DC));
#pragma unroll
        for (int s = 0; s < 16; s++) {
            int i = t + s * 256;
            cp16(smb + ST_CTX + i * 16, gctx + i * 16);
        }
        const char* gqk = (const char*)(g_Qk + (size_t)r * (NHEADS * DC));
        cp16(smb + ST_QK + t * 16, gqk + t * 16);
        cp16(smb + ST_QK + (t + 256) * 16, gqk + (t + 256) * 16);
        if (t < 16)
            cp16(smb + ST_BI + t * 16, (const char*)(bias + (size_t)r * MTOK) + t * 16);
        else if (t < 32)
            cp16(smb + ST_MK + (t - 16) * 16, (const char*)(mask + (size_t)r * MTOK) + (t - 16) * 16);
        CP_COMMIT();
    };

    issue_stage(r0);

    for (int g = 0; g < AC_G; g++) {
        const int r = r0 + g;
        CP_WAIT0();
        __syncthreads();                    // staging visible to all

        // ---- convert: staging fp32 -> bf16 hi/lo work layout ----
#pragma unroll
        for (int s = 0; s < 16; s++) {
            int i = t + s * 256;
            int m = i >> 6, c4 = i & 63;
            float4 v = *(const float4*)(sm + ST_CTX + i * 16);
            uint2 hi, lo; split_pack(v, hi, lo);
            *(uint2*)(sm + AC_CH + m * AC_LDC + c4 * 8) = hi;
            *(uint2*)(sm + AC_CL + m * AC_LDC + c4 * 8) = lo;
        }
#pragma unroll
        for (int s = 0; s < 2; s++) {
            int i = t + s * 256;
            int h = i >> 6, c4 = i & 63;
            float4 v = *(const float4*)(sm + ST_QK + i * 16);
            uint2 hi, lo; split_pack(v, hi, lo);
            *(uint2*)(sm + AC_QH + h * AC_LDC + c4 * 8) = hi;
            *(uint2*)(sm + AC_QL + h * AC_LDC + c4 * 8) = lo;
        }
        if (t < MTOK) {
            ((float*)(sm + AC_WB))[t] = ((const float*)(sm + ST_BI))[t];
            ((int*)(sm + AC_WM))[t]   = ((const int*)(sm + ST_MK))[t];
        }
        __syncthreads();                    // work ready; staging free

        if (g + 1 < AC_G) issue_stage(r + 1);   // stream next row during MMAs

        // ---- P1: scores. warp: m-tile (w&3), K-half (w>>2) ----
        {
            const int mtile = wid & 3, khalf = wid >> 2;
            float d[4] = {0.f, 0.f, 0.f, 0.f};
            const uint32_t a_base = smb + AC_CH +
                (uint32_t)((mtile * 16 + (lane & 15)) * AC_LDC + (lane >> 4) * 16);
            const uint32_t b_base = smb + AC_QH +
                (uint32_t)((lane & 7) * AC_LDC + ((lane >> 3) & 1) * 16);
#pragma unroll
            for (int j = 0; j < 8; j++) {
                const int kk = khalf * 8 + j;
                uint32_t ah[4], al[4], bh[2], bl[2];
                ldm_x4(ah, a_base + kk * 32);
                ldm_x4(al, a_base + kk * 32 + (AC_CL - AC_CH));
                ldm_x2(bh, b_base + kk * 32);
                ldm_x2(bl, b_base + kk * 32 + (AC_QL - AC_QH));
                mma_bf16(d, ah, bh);
                mma_bf16(d, ah, bl);
                mma_bf16(d, al, bh);
            }
            float* ss = (float*)(sm + (khalf ? AC_SB : AC_SA));
            const int gg = lane >> 2, tq = lane & 3;
            const int m0 = mtile * 16 + gg;
            ss[m0 * 9 + 2 * tq]           = d[0];
            ss[m0 * 9 + 2 * tq + 1]       = d[1];
            ss[(m0 + 8) * 9 + 2 * tq]     = d[2];
            ss[(m0 + 8) * 9 + 2 * tq + 1] = d[3];
        }
        __syncthreads();

        // ---- softmax: warp w = head h ----
        {
            const int w = wid;
            const float* sa = (const float*)(sm + AC_SA);
            const float* sb = (const float*)(sm + AC_SB);
            const float* sbias = (const float*)(sm + AC_WB);
            const int*   smask = (const int*)(sm + AC_WM);
            const int m0 = lane, m1 = lane + 32;
            float v0 = (sa[m0 * 9 + w] + sb[m0 * 9 + w]) * 0.125f + sbias[m0];
            float v1 = (sa[m1 * 9 + w] + sb[m1 * 9 + w]) * 0.125f + sbias[m1];
            if (!smask[m0]) v0 = -INFINITY;
            if (!smask[m1]) v1 = -INFINITY;
            float mx = fmaxf(v0, v1);
#pragma unroll
            for (int o = 16; o; o >>= 1) mx = fmaxf(mx, __shfl_xor_sync(0xffffffffu, mx, o));
            float e0 = __expf(v0 - mx);
            float e1 = __expf(v1 - mx);
            float s = e0 + e1;
#pragma unroll
            for (int o = 16; o; o >>= 1) s += __shfl_xor_sync(0xffffffffu, s, o);
            float inv = 1.0f / s;
            float a0 = e0 * inv, a1 = e1 * inv;
            __nv_bfloat16 h0 = __float2bfloat16_rn(a0);
            __nv_bfloat16 h1 = __float2bfloat16_rn(a1);
            __nv_bfloat16 l0 = __float2bfloat16_rn(a0 - __bfloat162float(h0));
            __nv_bfloat16 l1 = __float2bfloat16_rn(a1 - __bfloat162float(h1));
            uint16_t* ah = (uint16_t*)(sm + AC_AH);
            uint16_t* al = (uint16_t*)(sm + AC_AL);
            ah[m0 * 24 + w] = *(uint16_t*)&h0;
            ah[m1 * 24 + w] = *(uint16_t*)&h1;
            al[m0 * 24 + w] = *(uint16_t*)&l0;
            al[m1 * 24 + w] = *(uint16_t*)&l1;
        }
        __syncthreads();

        // ---- P3: D[c][h] = ctx^T . attn^T ; warp w owns c-tiles 2w, 2w+1 ----
        {
            float d0[4] = {0.f, 0.f, 0.f, 0.f};
            float d1[4] = {0.f, 0.f, 0.f, 0.f};
            const int c0 = wid * 32;
            const uint32_t bt_base = smb + AC_AH +
                (uint32_t)((((lane >> 3) & 1) * 8 + (lane & 7)) * 48);
            const uint32_t at_row = (uint32_t)(((lane >> 4) & 1) * 8 + (lane & 7));
            const uint32_t at_col = (uint32_t)(((lane >> 3) & 1) * 16);
#pragma unroll
            for (int kk = 0; kk < 4; kk++) {
                uint32_t bh[2], bl[2];
                ldm_x2_t(bh, bt_base + kk * 16 * 48);
                ldm_x2_t(bl, bt_base + kk * 16 * 48 + (AC_AL - AC_AH));
                const uint32_t arow = smb + AC_CH + (kk * 16 + at_row) * AC_LDC + at_col;
                uint32_t ah0[4], al0[4], ah1[4], al1[4];
                ldm_x4_t(ah0, arow + c0 * 2);
                ldm_x4_t(al0, arow + c0 * 2 + (AC_CL - AC_CH));
                ldm_x4_t(ah1, arow + (c0 + 16) * 2);
                ldm_x4_t(al1, arow + (c0 + 16) * 2 + (AC_CL - AC_CH));
                mma_bf16(d0, ah0, bh);
                mma_bf16(d0, ah0, bl);
                mma_bf16(d0, al0, bh);
                mma_bf16(d1, ah1, bh);
                mma_bf16(d1, ah1, bl);
                mma_bf16(d1, al1, bh);
            }
            const int gg = lane >> 2, tq = lane & 3;
            float* o = g_ctxA + (size_t)r * (NHEADS * DC);
            int c = c0 + gg;
            o[(2 * tq) * DC + c]         = d0[0];
            o[(2 * tq + 1) * DC + c]     = d0[1];
            o[(2 * tq) * DC + c + 8]     = d0[2];
            o[(2 * tq + 1) * DC + c + 8] = d0[3];
            c = c0 + 16 + gg;
            o[(2 * tq) * DC + c]         = d1[0];
            o[(2 * tq + 1) * DC + c]     = d1[1];
            o[(2 * tq) * DC + c + 8]     = d1[2];
            o[(2 * tq + 1) * DC + c + 8] = d1[3];
        }
        // loop-top CP_WAIT0 + __syncthreads separates P3 reads from next convert
    }
}

// ---------------------------------------------------------------------------
extern "C" void kernel_launch(void* const* d_in, const int* in_sizes, int n_in,
                              void* d_out, int out_size)
{
    const float* x    = (const float*)d_in[0];
    const float* ctx  = (const float*)d_in[1];
    const int*   mask = (const int*)d_in[2];
    const float* bias = (const float*)d_in[3];
    const float* Wq   = (const float*)d_in[4];
    const float* Wk   = (const float*)d_in[5];
    const float* Wv   = (const float*)d_in[6];
    const float* Wo   = (const float*)d_in[7];
    const float* bo   = (const float*)d_in[8];
    float*       out  = (float*)d_out;

    float *Qp, *Qkp, *cAp, *O1p, *WqTp, *WoTp, *WvTp;
    cudaGetSymbolAddress((void**)&Qp,   g_Q);
    cudaGetSymbolAddress((void**)&Qkp,  g_Qk);
    cudaGetSymbolAddress((void**)&cAp,  g_ctxA);
    cudaGetSymbolAddress((void**)&O1p,  g_O1);
    cudaGetSymbolAddress((void**)&WqTp, g_WqT);
    cudaGetSymbolAddress((void**)&WoTp, g_WoT);
    cudaGetSymbolAddress((void**)&WvTp, g_WvT);

    const int SM128 = 2 * (2 * 128 * LROWB + 2 * 128 * LROWB);
    const int SM64  = 2 * (2 * 128 * LROWB + 2 * 64 * LROWB);
    cudaFuncSetAttribute((const void*)hgemm<128, 2, 4, false>,
                         cudaFuncAttributeMaxDynamicSharedMemorySize, SM128);
    cudaFuncSetAttribute((const void*)hgemm<128, 2, 4, true>,
                         cudaFuncAttributeMaxDynamicSharedMemorySize, SM128);
    cudaFuncSetAttribute((const void*)hgemm<64, 4, 2, false>,
                         cudaFuncAttributeMaxDynamicSharedMemorySize, SM64);
    cudaFuncSetAttribute((const void*)attn_core,
                         cudaFuncAttributeMaxDynamicSharedMemorySize, AC_BYTES);

    dim3 tb(32, 8);
    transpose_k<<<dim3(16, 16), tb>>>(Wq, WqTp, DQ, INNER);
    transpose_k<<<dim3(16, 16), tb>>>(Wo, WoTp, INNER, DQ);
    transpose_k<<<dim3(16, 8),  tb>>>(Wv, WvTp, DC, INNER);

    // K1: Q = x @ Wq
    hgemm<128, 2, 4, false><<<dim3(INNER / 128, R_TOTAL / 128, 1), 256, SM128>>>(
        x, DQ, 0, WqTp, DQ, 0, Qp, INNER, 0, nullptr, DQ);

    // K2: Qk[r, h*256+c] = sum_d Q[r, h*64+d] * Wk[c, h*64+d]
    hgemm<128, 2, 4, false><<<dim3(DC / 128, R_TOTAL / 128, NHEADS), 256, SM128>>>(
        Qp, INNER, DHEAD, Wk, INNER, DHEAD, Qkp, NHEADS * DC, DC, nullptr, DHEAD);

    // K3: streaming fused attention core
    attn_core<<<R_TOTAL / AC_G, 256, AC_BYTES>>>(ctx, mask, bias);

    // K4: O1[r, h*64+d] = sum_c ctxA[r, h*256+c] * WvT[h*64+d, c]
    hgemm<64, 4, 2, false><<<dim3(1, R_TOTAL / 128, NHEADS), 256, SM64>>>(
        cAp, NHEADS * DC, DC, WvTp, DC, (long long)DHEAD * DC,
        O1p, INNER, DHEAD, nullptr, DC);

    // K5: out = O1 @ Wo + bo
    hgemm<128, 2, 4, true><<<dim3(DQ / 128, R_TOTAL / 128, 1), 256, SM128>>>(
        O1p, INNER, 0, WoTp, INNER, 0, out, DQ, 0, bo, INNER);
}

// round 7
// speedup vs baseline: 1.0942x; 1.0942x over previous
#include <cuda_runtime.h>
#include <cuda_bf16.h>
#include <math.h>
#include <stdint.h>

// Shapes (fixed)
#define R_TOTAL 4096
#define DQ      512
#define DC      256
#define MTOK    64
#define NHEADS  8
#define DHEAD   64
#define INNER   512

// Scratch (no allocs allowed)
__device__ float g_Q   [R_TOTAL * INNER];
__device__ float g_Qk  [R_TOTAL * NHEADS * DC];
__device__ float g_ctxA[R_TOTAL * NHEADS * DC];
__device__ float g_O1  [R_TOTAL * INNER];
__device__ float g_WqT [INNER * DQ];
__device__ float g_WoT [DQ * INNER];
__device__ float g_WvT [INNER * DC];

// ---------------- helpers ----------------
__device__ __forceinline__ uint32_t smem_u32(const void* p) {
    uint32_t a;
    asm("{ .reg .u64 t; cvta.to.shared.u64 t, %1; cvt.u32.u64 %0, t; }"
        : "=r"(a) : "l"(p));
    return a;
}
__device__ __forceinline__ void ldm_x4(uint32_t* r, uint32_t addr) {
    asm volatile("ldmatrix.sync.aligned.m8n8.x4.shared.b16 {%0,%1,%2,%3}, [%4];"
                 : "=r"(r[0]), "=r"(r[1]), "=r"(r[2]), "=r"(r[3]) : "r"(addr));
}
__device__ __forceinline__ void ldm_x2(uint32_t* r, uint32_t addr) {
    asm volatile("ldmatrix.sync.aligned.m8n8.x2.shared.b16 {%0,%1}, [%2];"
                 : "=r"(r[0]), "=r"(r[1]) : "r"(addr));
}
__device__ __forceinline__ void ldm_x4_t(uint32_t* r, uint32_t addr) {
    asm volatile("ldmatrix.sync.aligned.m8n8.x4.trans.shared.b16 {%0,%1,%2,%3}, [%4];"
                 : "=r"(r[0]), "=r"(r[1]), "=r"(r[2]), "=r"(r[3]) : "r"(addr));
}
__device__ __forceinline__ void ldm_x2_t(uint32_t* r, uint32_t addr) {
    asm volatile("ldmatrix.sync.aligned.m8n8.x2.trans.shared.b16 {%0,%1}, [%2];"
                 : "=r"(r[0]), "=r"(r[1]) : "r"(addr));
}
__device__ __forceinline__ void mma_bf16(float* c, const uint32_t* a, const uint32_t* b) {
    asm volatile("mma.sync.aligned.m16n8k16.row.col.f32.bf16.bf16.f32 "
                 "{%0,%1,%2,%3}, {%4,%5,%6,%7}, {%8,%9}, {%0,%1,%2,%3};"
                 : "+f"(c[0]), "+f"(c[1]), "+f"(c[2]), "+f"(c[3])
                 : "r"(a[0]), "r"(a[1]), "r"(a[2]), "r"(a[3]), "r"(b[0]), "r"(b[1]));
}
__device__ __forceinline__ uint32_t pack2(__nv_bfloat16 a, __nv_bfloat16 b) {
    uint16_t ua = *(uint16_t*)&a, ub = *(uint16_t*)&b;
    return (uint32_t)ua | ((uint32_t)ub << 16);
}
__device__ __forceinline__ void split_pack(float4 v, uint2& hi, uint2& lo) {
    __nv_bfloat16 hx = __float2bfloat16_rn(v.x);
    __nv_bfloat16 hy = __float2bfloat16_rn(v.y);
    __nv_bfloat16 hz = __float2bfloat16_rn(v.z);
    __nv_bfloat16 hw = __float2bfloat16_rn(v.w);
    __nv_bfloat16 lx = __float2bfloat16_rn(v.x - __bfloat162float(hx));
    __nv_bfloat16 ly = __float2bfloat16_rn(v.y - __bfloat162float(hy));
    __nv_bfloat16 lz = __float2bfloat16_rn(v.z - __bfloat162float(hz));
    __nv_bfloat16 lw = __float2bfloat16_rn(v.w - __bfloat162float(hw));
    hi = make_uint2(pack2(hx, hy), pack2(hz, hw));
    lo = make_uint2(pack2(lx, ly), pack2(lz, lw));
}

// ---------------------------------------------------------------------------
// bf16 3-term mma.sync GEMM; BM now templated. 256 threads, 2 CTAs/SM target.
// ---------------------------------------------------------------------------
#define LROW 40
#define LROWB 80

template<int BM, int BN, int MW, int NW, bool BIAS>
__global__ __launch_bounds__(256, 2)
void hgemm(const float* __restrict__ A, int lda, long long bsA,
           const float* __restrict__ B, int ldb, long long bsB,
           float* __restrict__ C, int ldc, long long bsC,
           const float* __restrict__ bias, int K)
{
    constexpr int WM = BM / MW;
    constexpr int WN = BN / NW;
    constexpr int MT = WM / 16;
    constexpr int NT = WN / 8;
    constexpr int A_BYTES = BM * LROWB;
    constexpr int B_BYTES = BN * LROWB;
    constexpr int STAGE = 2 * A_BYTES + 2 * B_BYTES;

    extern __shared__ char smc[];
    const uint32_t smb = smem_u32(smc);

    const int t = threadIdx.x;
    const int wid = t >> 5, lane = t & 31;
    const int wr = wid / NW, wc = wid % NW;
    const int wm = wr * WM, wn = wc * WN;
    const int bm = blockIdx.y * BM, bn = blockIdx.x * BN;

    A += (long long)blockIdx.z * bsA;
    B += (long long)blockIdx.z * bsB;
    C += (long long)blockIdx.z * bsC;

    const int rloc = t >> 3;
    const int f4   = t & 7;

    float acc[MT][NT][4];
#pragma unroll
    for (int i = 0; i < MT; i++)
#pragma unroll
        for (int j = 0; j < NT; j++)
#pragma unroll
            for (int q = 0; q < 4; q++) acc[i][j][q] = 0.0f;

    const int ns = K >> 5;
    float4 pa[BM / 32], pb[BN / 32];

    const uint32_t a_off = (uint32_t)(((wm + (lane & 15)) * LROW + (lane >> 4) * 8) * 2);
    const uint32_t b_off = (uint32_t)(((wn + (lane & 7)) * LROW + ((lane >> 3) & 1) * 8) * 2);

    auto gload = [&](int s) {
#pragma unroll
        for (int i = 0; i < BM / 32; i++)
            pa[i] = *(const float4*)(A + (long long)(bm + rloc + i * 32) * lda + s * 32 + f4 * 4);
#pragma unroll
        for (int i = 0; i < BN / 32; i++)
            pb[i] = *(const float4*)(B + (long long)(bn + rloc + i * 32) * ldb + s * 32 + f4 * 4);
    };
    auto sstore = [&](int buf) {
        char* base = smc + buf * STAGE;
#pragma unroll
        for (int i = 0; i < BM / 32; i++) {
            uint2 hi, lo; split_pack(pa[i], hi, lo);
            int r = rloc + i * 32;
            *(uint2*)(base + r * LROWB + f4 * 8)           = hi;
            *(uint2*)(base + A_BYTES + r * LROWB + f4 * 8) = lo;
        }
        char* bb = base + 2 * A_BYTES;
#pragma unroll
        for (int i = 0; i < BN / 32; i++) {
            uint2 hi, lo; split_pack(pb[i], hi, lo);
            int r = rloc + i * 32;
            *(uint2*)(bb + r * LROWB + f4 * 8)           = hi;
            *(uint2*)(bb + B_BYTES + r * LROWB + f4 * 8) = lo;
        }
    };
    auto compute = [&](int buf) {
        const uint32_t sa = smb + buf * STAGE;
        const uint32_t sb = sa + 2 * A_BYTES;
#pragma unroll
        for (int ks = 0; ks < 2; ks++) {
            uint32_t afh[MT][4], afl[MT][4], bfh[NT][2], bfl[NT][2];
#pragma unroll
            for (int mt = 0; mt < MT; mt++) {
                uint32_t ad = sa + a_off + mt * (16 * LROWB) + ks * 32;
                ldm_x4(afh[mt], ad);
                ldm_x4(afl[mt], ad + A_BYTES);
            }
#pragma unroll
            for (int nt = 0; nt < NT; nt++) {
                uint32_t bd = sb + b_off + nt * (8 * LROWB) + ks * 32;
                ldm_x2(bfh[nt], bd);
                ldm_x2(bfl[nt], bd + B_BYTES);
            }
#pragma unroll
            for (int mt = 0; mt < MT; mt++)
#pragma unroll
                for (int nt = 0; nt < NT; nt++) {
                    mma_bf16(acc[mt][nt], afh[mt], bfh[nt]);
                    mma_bf16(acc[mt][nt], afh[mt], bfl[nt]);
                    mma_bf16(acc[mt][nt], afl[mt], bfh[nt]);
                }
        }
    };

    gload(0);
    sstore(0);
    __syncthreads();
    for (int s = 0; s < ns; s++) {
        if (s + 1 < ns) gload(s + 1);
        compute(s & 1);
        if (s + 1 < ns) {
            sstore((s + 1) & 1);
            __syncthreads();
        }
    }

    const int g = lane >> 2, tq = lane & 3;
#pragma unroll
    for (int mt = 0; mt < MT; mt++) {
        int r0 = bm + wm + mt * 16 + g;
#pragma unroll
        for (int nt = 0; nt < NT; nt++) {
            int col = bn + wn + nt * 8 + tq * 2;
            float b0 = 0.f, b1 = 0.f;
            if (BIAS) { b0 = bias[col]; b1 = bias[col + 1]; }
            *(float2*)(C + (long long)r0 * ldc + col) =
                make_float2(acc[mt][nt][0] + b0, acc[mt][nt][1] + b1);
            *(float2*)(C + (long long)(r0 + 8) * ldc + col) =
                make_float2(acc[mt][nt][2] + b0, acc[mt][nt][3] + b1);
        }
    }
}

// ---------------------------------------------------------------------------
// Weight transpose
// ---------------------------------------------------------------------------
__global__ void transpose_k(const float* __restrict__ src, float* __restrict__ dst,
                            int R, int C)
{
    __shared__ float tile[32][33];
    int bx = blockIdx.x * 32, by = blockIdx.y * 32;
#pragma unroll
    for (int j = 0; j < 32; j += 8)
        tile[threadIdx.y + j][threadIdx.x] =
            src[(long long)(by + threadIdx.y + j) * C + bx + threadIdx.x];
    __syncthreads();
#pragma unroll
    for (int j = 0; j < 32; j += 8)
        dst[(long long)(bx + threadIdx.y + j) * R + by + threadIdx.x] =
            tile[threadIdx.x][threadIdx.y + j];
}

// ---------------------------------------------------------------------------
// Tensor-core attention core (round-5 passing version, 1 CTA per row).
// ---------------------------------------------------------------------------
#define AC_LDC 528
#define AC_CH 0
#define AC_CL 33792
#define AC_QH 67584
#define AC_QL 71808
#define AC_AH 76032
#define AC_AL 79104
#define AC_SA 82176
#define AC_SB 84480
#define AC_BI 86784
#define AC_MK 87040
#define AC_BYTES 87296

__global__ __launch_bounds__(256)
void attn_core(const float* __restrict__ ctx,
               const int* __restrict__ mask,
               const float* __restrict__ bias)
{
    extern __shared__ char sm[];
    const uint32_t smb = smem_u32(sm);
    const int r = blockIdx.x, t = threadIdx.x;
    const int wid = t >> 5, lane = t & 31;

    // ---- phase 0: load + bf16 split ----
    {
        const float4* g = (const float4*)(ctx + (size_t)r * (MTOK * DC));
#pragma unroll
        for (int s = 0; s < 16; s++) {
            int i = t + s * 256;
            int m = i >> 6, c4 = i & 63;
            uint2 hi, lo; split_pack(g[i], hi, lo);
            *(uint2*)(sm + AC_CH + m * AC_LDC + c4 * 8) = hi;
            *(uint2*)(sm + AC_CL + m * AC_LDC + c4 * 8) = lo;
        }
        const float4* gq = (const float4*)(g_Qk + (size_t)r * (NHEADS * DC));
#pragma unroll
        for (int s = 0; s < 2; s++) {
            int i = t + s * 256;
            int h = i >> 6, c4 = i & 63;
            uint2 hi, lo; split_pack(gq[i], hi, lo);
            *(uint2*)(sm + AC_QH + h * AC_LDC + c4 * 8) = hi;
            *(uint2*)(sm + AC_QL + h * AC_LDC + c4 * 8) = lo;
        }
        if (t < MTOK) {
            ((float*)(sm + AC_BI))[t] = bias[(size_t)r * MTOK + t];
            ((int*)(sm + AC_MK))[t]   = mask[(size_t)r * MTOK + t];
        }
    }
    __syncthreads();

    // ---- phase 1: scores ----
    {
        const int mtile = wid & 3, khalf = wid >> 2;
        float d[4] = {0.f, 0.f, 0.f, 0.f};
        const uint32_t a_base = smb + AC_CH +
            (uint32_t)((mtile * 16 + (lane & 15)) * AC_LDC + (lane >> 4) * 16);
        const uint32_t b_base = smb + AC_QH +
            (uint32_t)((lane & 7) * AC_LDC + ((lane >> 3) & 1) * 16);
#pragma unroll
        for (int j = 0; j < 8; j++) {
            const int kk = khalf * 8 + j;
            uint32_t ah[4], al[4], bh[2], bl[2];
            ldm_x4(ah, a_base + kk * 32);
            ldm_x4(al, a_base + kk * 32 + (AC_CL - AC_CH));
            ldm_x2(bh, b_base + kk * 32);
            ldm_x2(bl, b_base + kk * 32 + (AC_QL - AC_QH));
            mma_bf16(d, ah, bh);
            mma_bf16(d, ah, bl);
            mma_bf16(d, al, bh);
        }
        float* ss = (float*)(sm + (khalf ? AC_SB : AC_SA));
        const int gg = lane >> 2, tq = lane & 3;
        const int m0 = mtile * 16 + gg;
        ss[m0 * 9 + 2 * tq]           = d[0];
        ss[m0 * 9 + 2 * tq + 1]       = d[1];
        ss[(m0 + 8) * 9 + 2 * tq]     = d[2];
        ss[(m0 + 8) * 9 + 2 * tq + 1] = d[3];
    }
    __syncthreads();

    // ---- softmax: warp w = head h ----
    {
        const int w = wid;
        const float* sa = (const float*)(sm + AC_SA);
        const float* sb = (const float*)(sm + AC_SB);
        const float* sbias = (const float*)(sm + AC_BI);
        const int*   smask = (const int*)(sm + AC_MK);
        const int m0 = lane, m1 = lane + 32;
        float v0 = (sa[m0 * 9 + w] + sb[m0 * 9 + w]) * 0.125f + sbias[m0];
        float v1 = (sa[m1 * 9 + w] + sb[m1 * 9 + w]) * 0.125f + sbias[m1];
        if (!smask[m0]) v0 = -INFINITY;
        if (!smask[m1]) v1 = -INFINITY;
        float mx = fmaxf(v0, v1);
#pragma unroll
        for (int o = 16; o; o >>= 1) mx = fmaxf(mx, __shfl_xor_sync(0xffffffffu, mx, o));
        float e0 = __expf(v0 - mx);
        float e1 = __expf(v1 - mx);
        float s = e0 + e1;
#pragma unroll
        for (int o = 16; o; o >>= 1) s += __shfl_xor_sync(0xffffffffu, s, o);
        float inv = 1.0f / s;
        float a0 = e0 * inv, a1 = e1 * inv;
        __nv_bfloat16 h0 = __float2bfloat16_rn(a0);
        __nv_bfloat16 h1 = __float2bfloat16_rn(a1);
        __nv_bfloat16 l0 = __float2bfloat16_rn(a0 - __bfloat162float(h0));
        __nv_bfloat16 l1 = __float2bfloat16_rn(a1 - __bfloat162float(h1));
        uint16_t* ah = (uint16_t*)(sm + AC_AH);
        uint16_t* al = (uint16_t*)(sm + AC_AL);
        ah[m0 * 24 + w] = *(uint16_t*)&h0;
        ah[m1 * 24 + w] = *(uint16_t*)&h1;
        al[m0 * 24 + w] = *(uint16_t*)&l0;
        al[m1 * 24 + w] = *(uint16_t*)&l1;
    }
    __syncthreads();

    // ---- phase 3: D[c][h] ----
    {
        float d0[4] = {0.f, 0.f, 0.f, 0.f};
        float d1[4] = {0.f, 0.f, 0.f, 0.f};
        const int c0 = wid * 32;
        const uint32_t bt_base = smb + AC_AH +
            (uint32_t)((((lane >> 3) & 1) * 8 + (lane & 7)) * 48);
        const uint32_t at_row = (uint32_t)(((lane >> 4) & 1) * 8 + (lane & 7));
        const uint32_t at_col = (uint32_t)(((lane >> 3) & 1) * 16);
#pragma unroll
        for (int kk = 0; kk < 4; kk++) {
            uint32_t bh[2], bl[2];
            ldm_x2_t(bh, bt_base + kk * 16 * 48);
            ldm_x2_t(bl, bt_base + kk * 16 * 48 + (AC_AL - AC_AH));
            const uint32_t arow = smb + AC_CH + (kk * 16 + at_row) * AC_LDC + at_col;
            uint32_t ah0[4], al0[4], ah1[4], al1[4];
            ldm_x4_t(ah0, arow + c0 * 2);
            ldm_x4_t(al0, arow + c0 * 2 + (AC_CL - AC_CH));
            ldm_x4_t(ah1, arow + (c0 + 16) * 2);
            ldm_x4_t(al1, arow + (c0 + 16) * 2 + (AC_CL - AC_CH));
            mma_bf16(d0, ah0, bh);
            mma_bf16(d0, ah0, bl);
            mma_bf16(d0, al0, bh);
            mma_bf16(d1, ah1, bh);
            mma_bf16(d1, ah1, bl);
            mma_bf16(d1, al1, bh);
        }
        const int gg = lane >> 2, tq = lane & 3;
        float* o = g_ctxA + (size_t)r * (NHEADS * DC);
        int c = c0 + gg;
        o[(2 * tq) * DC + c]         = d0[0];
        o[(2 * tq + 1) * DC + c]     = d0[1];
        o[(2 * tq) * DC + c + 8]     = d0[2];
        o[(2 * tq + 1) * DC + c + 8] = d0[3];
        c = c0 + 16 + gg;
        o[(2 * tq) * DC + c]         = d1[0];
        o[(2 * tq + 1) * DC + c]     = d1[1];
        o[(2 * tq) * DC + c + 8]     = d1[2];
        o[(2 * tq + 1) * DC + c + 8] = d1[3];
    }
}

// ---------------------------------------------------------------------------
extern "C" void kernel_launch(void* const* d_in, const int* in_sizes, int n_in,
                              void* d_out, int out_size)
{
    const float* x    = (const float*)d_in[0];
    const float* ctx  = (const float*)d_in[1];
    const int*   mask = (const int*)d_in[2];
    const float* bias = (const float*)d_in[3];
    const float* Wq   = (const float*)d_in[4];
    const float* Wk   = (const float*)d_in[5];
    const float* Wv   = (const float*)d_in[6];
    const float* Wo   = (const float*)d_in[7];
    const float* bo   = (const float*)d_in[8];
    float*       out  = (float*)d_out;

    float *Qp, *Qkp, *cAp, *O1p, *WqTp, *WoTp, *WvTp;
    cudaGetSymbolAddress((void**)&Qp,   g_Q);
    cudaGetSymbolAddress((void**)&Qkp,  g_Qk);
    cudaGetSymbolAddress((void**)&cAp,  g_ctxA);
    cudaGetSymbolAddress((void**)&O1p,  g_O1);
    cudaGetSymbolAddress((void**)&WqTp, g_WqT);
    cudaGetSymbolAddress((void**)&WoTp, g_WoT);
    cudaGetSymbolAddress((void**)&WvTp, g_WvT);

    // smem: 2 stages * (2*BM*80 + 2*BN*80)
    const int SM_64_128 = 2 * (2 * 64 * LROWB + 2 * 128 * LROWB);   // 61440
    const int SM_64_64  = 2 * (2 * 64 * LROWB + 2 * 64 * LROWB);    // 40960
    cudaFuncSetAttribute((const void*)hgemm<64, 128, 2, 4, false>,
                         cudaFuncAttributeMaxDynamicSharedMemorySize, SM_64_128);
    cudaFuncSetAttribute((const void*)hgemm<64, 128, 2, 4, true>,
                         cudaFuncAttributeMaxDynamicSharedMemorySize, SM_64_128);
    cudaFuncSetAttribute((const void*)hgemm<64, 64, 2, 4, false>,
                         cudaFuncAttributeMaxDynamicSharedMemorySize, SM_64_64);
    cudaFuncSetAttribute((const void*)attn_core,
                         cudaFuncAttributeMaxDynamicSharedMemorySize, AC_BYTES);

    dim3 tb(32, 8);
    transpose_k<<<dim3(16, 16), tb>>>(Wq, WqTp, DQ, INNER);
    transpose_k<<<dim3(16, 16), tb>>>(Wo, WoTp, INNER, DQ);
    transpose_k<<<dim3(16, 8),  tb>>>(Wv, WvTp, DC, INNER);

    // K1: Q = x @ Wq   (grid 4 x 64 = 256 CTAs)
    hgemm<64, 128, 2, 4, false><<<dim3(INNER / 128, R_TOTAL / 64, 1), 256, SM_64_128>>>(
        x, DQ, 0, WqTp, DQ, 0, Qp, INNER, 0, nullptr, DQ);

    // K2: Qk (grid 2 x 64 x 8 = 1024 CTAs)
    hgemm<64, 128, 2, 4, false><<<dim3(DC / 128, R_TOTAL / 64, NHEADS), 256, SM_64_128>>>(
        Qp, INNER, DHEAD, Wk, INNER, DHEAD, Qkp, NHEADS * DC, DC, nullptr, DHEAD);

    // K3: fused attention core (round-5 version)
    attn_core<<<R_TOTAL, 256, AC_BYTES>>>(ctx, mask, bias);

    // K4: O1 (grid 1 x 64 x 8 = 512 CTAs)
    hgemm<64, 64, 2, 4, false><<<dim3(1, R_TOTAL / 64, NHEADS), 256, SM_64_64>>>(
        cAp, NHEADS * DC, DC, WvTp, DC, (long long)DHEAD * DC,
        O1p, INNER, DHEAD, nullptr, DC);

    // K5: out = O1 @ Wo + bo  (grid 4 x 64 = 256 CTAs)
    hgemm<64, 128, 2, 4, true><<<dim3(DQ / 128, R_TOTAL / 64, 1), 256, SM_64_128>>>(
        O1p, INNER, 0, WoTp, INNER, 0, out, DQ, 0, bo, INNER);
}

// round 8
// speedup vs baseline: 1.3211x; 1.2074x over previous
#include <cuda_runtime.h>
#include <cuda_fp16.h>
#include <math.h>
#include <stdint.h>

// Shapes (fixed)
#define R_TOTAL 4096
#define DQ      512
#define DC      256
#define MTOK    64
#define NHEADS  8
#define DHEAD   64
#define INNER   512

// Scratch (no allocs allowed)
__device__ float g_Q   [R_TOTAL * INNER];
__device__ float g_Qk  [R_TOTAL * NHEADS * DC];
__device__ float g_ctxA[R_TOTAL * NHEADS * DC];
__device__ float g_O1  [R_TOTAL * INNER];
__device__ float g_WqT [INNER * DQ];
__device__ float g_WoT [DQ * INNER];
__device__ float g_WvT [INNER * DC];

// ---------------- helpers ----------------
__device__ __forceinline__ uint32_t smem_u32(const void* p) {
    uint32_t a;
    asm("{ .reg .u64 t; cvta.to.shared.u64 t, %1; cvt.u32.u64 %0, t; }"
        : "=r"(a) : "l"(p));
    return a;
}
__device__ __forceinline__ void ldm_x4(uint32_t* r, uint32_t addr) {
    asm volatile("ldmatrix.sync.aligned.m8n8.x4.shared.b16 {%0,%1,%2,%3}, [%4];"
                 : "=r"(r[0]), "=r"(r[1]), "=r"(r[2]), "=r"(r[3]) : "r"(addr));
}
__device__ __forceinline__ void ldm_x2(uint32_t* r, uint32_t addr) {
    asm volatile("ldmatrix.sync.aligned.m8n8.x2.shared.b16 {%0,%1}, [%2];"
                 : "=r"(r[0]), "=r"(r[1]) : "r"(addr));
}
__device__ __forceinline__ void ldm_x4_t(uint32_t* r, uint32_t addr) {
    asm volatile("ldmatrix.sync.aligned.m8n8.x4.trans.shared.b16 {%0,%1,%2,%3}, [%4];"
                 : "=r"(r[0]), "=r"(r[1]), "=r"(r[2]), "=r"(r[3]) : "r"(addr));
}
__device__ __forceinline__ void ldm_x2_t(uint32_t* r, uint32_t addr) {
    asm volatile("ldmatrix.sync.aligned.m8n8.x2.trans.shared.b16 {%0,%1}, [%2];"
                 : "=r"(r[0]), "=r"(r[1]) : "r"(addr));
}
__device__ __forceinline__ void mma_f16(float* c, const uint32_t* a, const uint32_t* b) {
    asm volatile("mma.sync.aligned.m16n8k16.row.col.f32.f16.f16.f32 "
                 "{%0,%1,%2,%3}, {%4,%5,%6,%7}, {%8,%9}, {%0,%1,%2,%3};"
                 : "+f"(c[0]), "+f"(c[1]), "+f"(c[2]), "+f"(c[3])
                 : "r"(a[0]), "r"(a[1]), "r"(a[2]), "r"(a[3]), "r"(b[0]), "r"(b[1]));
}
// fp32x4 -> fp16x4 (hi only)
__device__ __forceinline__ uint2 pack_h(float4 v) {
    __half2 h01 = __float22half2_rn(make_float2(v.x, v.y));
    __half2 h23 = __float22half2_rn(make_float2(v.z, v.w));
    return make_uint2(*(uint32_t*)&h01, *(uint32_t*)&h23);
}
// fp32x4 -> (hi fp16x4, lo fp16x4), x = hi + lo to ~2^-22
__device__ __forceinline__ void split_h(float4 v, uint2& hi, uint2& lo) {
    __half hx = __float2half_rn(v.x);
    __half hy = __float2half_rn(v.y);
    __half hz = __float2half_rn(v.z);
    __half hw = __float2half_rn(v.w);
    __half2 h01; h01 = __halves2half2(hx, hy);
    __half2 h23; h23 = __halves2half2(hz, hw);
    __half2 l01 = __float22half2_rn(make_float2(v.x - __half2float(hx), v.y - __half2float(hy)));
    __half2 l23 = __float22half2_rn(make_float2(v.z - __half2float(hz), v.w - __half2float(hw)));
    hi = make_uint2(*(uint32_t*)&h01, *(uint32_t*)&h23);
    lo = make_uint2(*(uint32_t*)&l01, *(uint32_t*)&l23);
}

// ---------------------------------------------------------------------------
// fp16 2-term mma.sync GEMM: C = A·B^T (+bias). A split hi/lo (exact), B hi.
// BM templated; 256 threads; 2 CTAs/SM.
// ---------------------------------------------------------------------------
#define LROW 40
#define LROWB 80

template<int BM, int BN, int MW, int NW, bool BIAS>
__global__ __launch_bounds__(256, 2)
void hgemm(const float* __restrict__ A, int lda, long long bsA,
           const float* __restrict__ B, int ldb, long long bsB,
           float* __restrict__ C, int ldc, long long bsC,
           const float* __restrict__ bias, int K)
{
    constexpr int WM = BM / MW;
    constexpr int WN = BN / NW;
    constexpr int MT = WM / 16;
    constexpr int NT = WN / 8;
    constexpr int A_BYTES = BM * LROWB;     // hi region; lo at +A_BYTES
    constexpr int B_BYTES = BN * LROWB;     // hi only
    constexpr int STAGE = 2 * A_BYTES + B_BYTES;

    extern __shared__ char smc[];
    const uint32_t smb = smem_u32(smc);

    const int t = threadIdx.x;
    const int wid = t >> 5, lane = t & 31;
    const int wr = wid / NW, wc = wid % NW;
    const int wm = wr * WM, wn = wc * WN;
    const int bm = blockIdx.y * BM, bn = blockIdx.x * BN;

    A += (long long)blockIdx.z * bsA;
    B += (long long)blockIdx.z * bsB;
    C += (long long)blockIdx.z * bsC;

    const int rloc = t >> 3;
    const int f4   = t & 7;

    float acc[MT][NT][4];
#pragma unroll
    for (int i = 0; i < MT; i++)
#pragma unroll
        for (int j = 0; j < NT; j++)
#pragma unroll
            for (int q = 0; q < 4; q++) acc[i][j][q] = 0.0f;

    const int ns = K >> 5;
    float4 pa[BM / 32], pb[BN / 32];

    const uint32_t a_off = (uint32_t)(((wm + (lane & 15)) * LROW + (lane >> 4) * 8) * 2);
    const uint32_t b_off = (uint32_t)(((wn + (lane & 7)) * LROW + ((lane >> 3) & 1) * 8) * 2);

    auto gload = [&](int s) {
#pragma unroll
        for (int i = 0; i < BM / 32; i++)
            pa[i] = *(const float4*)(A + (long long)(bm + rloc + i * 32) * lda + s * 32 + f4 * 4);
#pragma unroll
        for (int i = 0; i < BN / 32; i++)
            pb[i] = *(const float4*)(B + (long long)(bn + rloc + i * 32) * ldb + s * 32 + f4 * 4);
    };
    auto sstore = [&](int buf) {
        char* base = smc + buf * STAGE;
#pragma unroll
        for (int i = 0; i < BM / 32; i++) {
            uint2 hi, lo; split_h(pa[i], hi, lo);
            int r = rloc + i * 32;
            *(uint2*)(base + r * LROWB + f4 * 8)           = hi;
            *(uint2*)(base + A_BYTES + r * LROWB + f4 * 8) = lo;
        }
        char* bb = base + 2 * A_BYTES;
#pragma unroll
        for (int i = 0; i < BN / 32; i++) {
            int r = rloc + i * 32;
            *(uint2*)(bb + r * LROWB + f4 * 8) = pack_h(pb[i]);
        }
    };
    auto compute = [&](int buf) {
        const uint32_t sa = smb + buf * STAGE;
        const uint32_t sb = sa + 2 * A_BYTES;
#pragma unroll
        for (int ks = 0; ks < 2; ks++) {
            uint32_t afh[MT][4], afl[MT][4], bfh[NT][2];
#pragma unroll
            for (int mt = 0; mt < MT; mt++) {
                uint32_t ad = sa + a_off + mt * (16 * LROWB) + ks * 32;
                ldm_x4(afh[mt], ad);
                ldm_x4(afl[mt], ad + A_BYTES);
            }
#pragma unroll
            for (int nt = 0; nt < NT; nt++) {
                uint32_t bd = sb + b_off + nt * (8 * LROWB) + ks * 32;
                ldm_x2(bfh[nt], bd);
            }
#pragma unroll
            for (int mt = 0; mt < MT; mt++)
#pragma unroll
                for (int nt = 0; nt < NT; nt++) {
                    mma_f16(acc[mt][nt], afh[mt], bfh[nt]);
                    mma_f16(acc[mt][nt], afl[mt], bfh[nt]);
                }
        }
    };

    gload(0);
    sstore(0);
    __syncthreads();
    for (int s = 0; s < ns; s++) {
        if (s + 1 < ns) gload(s + 1);
        compute(s & 1);
        if (s + 1 < ns) {
            sstore((s + 1) & 1);
            __syncthreads();
        }
    }

    const int g = lane >> 2, tq = lane & 3;
#pragma unroll
    for (int mt = 0; mt < MT; mt++) {
        int r0 = bm + wm + mt * 16 + g;
#pragma unroll
        for (int nt = 0; nt < NT; nt++) {
            int col = bn + wn + nt * 8 + tq * 2;
            float b0 = 0.f, b1 = 0.f;
            if (BIAS) { b0 = bias[col]; b1 = bias[col + 1]; }
            *(float2*)(C + (long long)r0 * ldc + col) =
                make_float2(acc[mt][nt][0] + b0, acc[mt][nt][1] + b1);
            *(float2*)(C + (long long)(r0 + 8) * ldc + col) =
                make_float2(acc[mt][nt][2] + b0, acc[mt][nt][3] + b1);
        }
    }
}

// ---------------------------------------------------------------------------
// Weight transpose
// ---------------------------------------------------------------------------
__global__ void transpose_k(const float* __restrict__ src, float* __restrict__ dst,
                            int R, int C)
{
    __shared__ float tile[32][33];
    int bx = blockIdx.x * 32, by = blockIdx.y * 32;
#pragma unroll
    for (int j = 0; j < 32; j += 8)
        tile[threadIdx.y + j][threadIdx.x] =
            src[(long long)(by + threadIdx.y + j) * C + bx + threadIdx.x];
    __syncthreads();
#pragma unroll
    for (int j = 0; j < 32; j += 8)
        dst[(long long)(bx + threadIdx.y + j) * R + by + threadIdx.x] =
            tile[threadIdx.x][threadIdx.y + j];
}

// ---------------------------------------------------------------------------
// Tensor-core attention core, fp16 2-term. One CTA per (b,l) row.
//   P1: S = ctx(hi+lo) . Qk(hi)^T ;  softmax ;  P3: D = ctx^T(hi+lo) . attn^T(hi)
// ---------------------------------------------------------------------------
#define AC_LDC 528
#define AC_CH 0          // ctx hi 64x528
#define AC_CL 33792      // ctx lo
#define AC_QH 67584      // qk hi 8x528
#define AC_AH 71808      // attn^T hi 64x48B
#define AC_SA 74880      // partial scores 64x9 f32
#define AC_SB 77184
#define AC_BI 79488
#define AC_MK 79744
#define AC_BYTES 80000

__global__ __launch_bounds__(256)
void attn_core(const float* __restrict__ ctx,
               const int* __restrict__ mask,
               const float* __restrict__ bias)
{
    extern __shared__ char sm[];
    const uint32_t smb = smem_u32(sm);
    const int r = blockIdx.x, t = threadIdx.x;
    const int wid = t >> 5, lane = t & 31;

    // ---- phase 0: load + fp16 split ----
    {
        const float4* g = (const float4*)(ctx + (size_t)r * (MTOK * DC));
#pragma unroll
        for (int s = 0; s < 16; s++) {
            int i = t + s * 256;
            int m = i >> 6, c4 = i & 63;
            uint2 hi, lo; split_h(g[i], hi, lo);
            *(uint2*)(sm + AC_CH + m * AC_LDC + c4 * 8) = hi;
            *(uint2*)(sm + AC_CL + m * AC_LDC + c4 * 8) = lo;
        }
        const float4* gq = (const float4*)(g_Qk + (size_t)r * (NHEADS * DC));
#pragma unroll
        for (int s = 0; s < 2; s++) {
            int i = t + s * 256;
            int h = i >> 6, c4 = i & 63;
            *(uint2*)(sm + AC_QH + h * AC_LDC + c4 * 8) = pack_h(gq[i]);
        }
        if (t < MTOK) {
            ((float*)(sm + AC_BI))[t] = bias[(size_t)r * MTOK + t];
            ((int*)(sm + AC_MK))[t]   = mask[(size_t)r * MTOK + t];
        }
    }
    __syncthreads();

    // ---- phase 1: scores. warp: m-tile (w&3), K-half (w>>2) ----
    {
        const int mtile = wid & 3, khalf = wid >> 2;
        float d[4] = {0.f, 0.f, 0.f, 0.f};
        const uint32_t a_base = smb + AC_CH +
            (uint32_t)((mtile * 16 + (lane & 15)) * AC_LDC + (lane >> 4) * 16);
        const uint32_t b_base = smb + AC_QH +
            (uint32_t)((lane & 7) * AC_LDC + ((lane >> 3) & 1) * 16);
#pragma unroll
        for (int j = 0; j < 8; j++) {
            const int kk = khalf * 8 + j;
            uint32_t ah[4], al[4], bh[2];
            ldm_x4(ah, a_base + kk * 32);
            ldm_x4(al, a_base + kk * 32 + (AC_CL - AC_CH));
            ldm_x2(bh, b_base + kk * 32);
            mma_f16(d, ah, bh);
            mma_f16(d, al, bh);
        }
        float* ss = (float*)(sm + (khalf ? AC_SB : AC_SA));
        const int gg = lane >> 2, tq = lane & 3;
        const int m0 = mtile * 16 + gg;
        ss[m0 * 9 + 2 * tq]           = d[0];
        ss[m0 * 9 + 2 * tq + 1]       = d[1];
        ss[(m0 + 8) * 9 + 2 * tq]     = d[2];
        ss[(m0 + 8) * 9 + 2 * tq + 1] = d[3];
    }
    __syncthreads();

    // ---- softmax: warp w = head h ----
    {
        const int w = wid;
        const float* sa = (const float*)(sm + AC_SA);
        const float* sb = (const float*)(sm + AC_SB);
        const float* sbias = (const float*)(sm + AC_BI);
        const int*   smask = (const int*)(sm + AC_MK);
        const int m0 = lane, m1 = lane + 32;
        float v0 = (sa[m0 * 9 + w] + sb[m0 * 9 + w]) * 0.125f + sbias[m0];
        float v1 = (sa[m1 * 9 + w] + sb[m1 * 9 + w]) * 0.125f + sbias[m1];
        if (!smask[m0]) v0 = -INFINITY;
        if (!smask[m1]) v1 = -INFINITY;
        float mx = fmaxf(v0, v1);
#pragma unroll
        for (int o = 16; o; o >>= 1) mx = fmaxf(mx, __shfl_xor_sync(0xffffffffu, mx, o));
        float e0 = __expf(v0 - mx);
        float e1 = __expf(v1 - mx);
        float s = e0 + e1;
#pragma unroll
        for (int o = 16; o; o >>= 1) s += __shfl_xor_sync(0xffffffffu, s, o);
        float inv = 1.0f / s;
        __half h0 = __float2half_rn(e0 * inv);
        __half h1 = __float2half_rn(e1 * inv);
        uint16_t* ah = (uint16_t*)(sm + AC_AH);
        ah[m0 * 24 + w] = *(uint16_t*)&h0;
        ah[m1 * 24 + w] = *(uint16_t*)&h1;
    }
    __syncthreads();

    // ---- phase 3: D[c][h] = ctx^T . attn^T ; warp w owns c-tiles 2w, 2w+1 ----
    {
        float d0[4] = {0.f, 0.f, 0.f, 0.f};
        float d1[4] = {0.f, 0.f, 0.f, 0.f};
        const int c0 = wid * 32;
        const uint32_t bt_base = smb + AC_AH +
            (uint32_t)((((lane >> 3) & 1) * 8 + (lane & 7)) * 48);
        const uint32_t at_row = (uint32_t)(((lane >> 4) & 1) * 8 + (lane & 7));
        const uint32_t at_col = (uint32_t)(((lane >> 3) & 1) * 16);
#pragma unroll
        for (int kk = 0; kk < 4; kk++) {
            uint32_t bh[2];
            ldm_x2_t(bh, bt_base + kk * 16 * 48);
            const uint32_t arow = smb + AC_CH + (kk * 16 + at_row) * AC_LDC + at_col;
            uint32_t ah0[4], al0[4], ah1[4], al1[4];
            ldm_x4_t(ah0, arow + c0 * 2);
            ldm_x4_t(al0, arow + c0 * 2 + (AC_CL - AC_CH));
            ldm_x4_t(ah1, arow + (c0 + 16) * 2);
            ldm_x4_t(al1, arow + (c0 + 16) * 2 + (AC_CL - AC_CH));
            mma_f16(d0, ah0, bh);
            mma_f16(d0, al0, bh);
            mma_f16(d1, ah1, bh);
            mma_f16(d1, al1, bh);
        }
        const int gg = lane >> 2, tq = lane & 3;
        float* o = g_ctxA + (size_t)r * (NHEADS * DC);
        int c = c0 + gg;
        o[(2 * tq) * DC + c]         = d0[0];
        o[(2 * tq + 1) * DC + c]     = d0[1];
        o[(2 * tq) * DC + c + 8]     = d0[2];
        o[(2 * tq + 1) * DC + c + 8] = d0[3];
        c = c0 + 16 + gg;
        o[(2 * tq) * DC + c]         = d1[0];
        o[(2 * tq + 1) * DC + c]     = d1[1];
        o[(2 * tq) * DC + c + 8]     = d1[2];
        o[(2 * tq + 1) * DC + c + 8] = d1[3];
    }
}

// ---------------------------------------------------------------------------
extern "C" void kernel_launch(void* const* d_in, const int* in_sizes, int n_in,
                              void* d_out, int out_size)
{
    const float* x    = (const float*)d_in[0];
    const float* ctx  = (const float*)d_in[1];
    const int*   mask = (const int*)d_in[2];
    const float* bias = (const float*)d_in[3];
    const float* Wq   = (const float*)d_in[4];
    const float* Wk   = (const float*)d_in[5];
    const float* Wv   = (const float*)d_in[6];
    const float* Wo   = (const float*)d_in[7];
    const float* bo   = (const float*)d_in[8];
    float*       out  = (float*)d_out;

    float *Qp, *Qkp, *cAp, *O1p, *WqTp, *WoTp, *WvTp;
    cudaGetSymbolAddress((void**)&Qp,   g_Q);
    cudaGetSymbolAddress((void**)&Qkp,  g_Qk);
    cudaGetSymbolAddress((void**)&cAp,  g_ctxA);
    cudaGetSymbolAddress((void**)&O1p,  g_O1);
    cudaGetSymbolAddress((void**)&WqTp, g_WqT);
    cudaGetSymbolAddress((void**)&WoTp, g_WoT);
    cudaGetSymbolAddress((void**)&WvTp, g_WvT);

    // smem: 2 stages * (2*BM*80 + BN*80)
    const int SM_64_128 = 2 * (2 * 64 * LROWB + 128 * LROWB);   // 40960
    const int SM_64_64  = 2 * (2 * 64 * LROWB + 64 * LROWB);    // 30720
    cudaFuncSetAttribute((const void*)hgemm<64, 128, 2, 4, false>,
                         cudaFuncAttributeMaxDynamicSharedMemorySize, SM_64_128);
    cudaFuncSetAttribute((const void*)hgemm<64, 128, 2, 4, true>,
                         cudaFuncAttributeMaxDynamicSharedMemorySize, SM_64_128);
    cudaFuncSetAttribute((const void*)hgemm<64, 64, 2, 4, false>,
                         cudaFuncAttributeMaxDynamicSharedMemorySize, SM_64_64);
    cudaFuncSetAttribute((const void*)attn_core,
                         cudaFuncAttributeMaxDynamicSharedMemorySize, AC_BYTES);

    dim3 tb(32, 8);
    transpose_k<<<dim3(16, 16), tb>>>(Wq, WqTp, DQ, INNER);
    transpose_k<<<dim3(16, 16), tb>>>(Wo, WoTp, INNER, DQ);
    transpose_k<<<dim3(16, 8),  tb>>>(Wv, WvTp, DC, INNER);

    // K1: Q = x @ Wq
    hgemm<64, 128, 2, 4, false><<<dim3(INNER / 128, R_TOTAL / 64, 1), 256, SM_64_128>>>(
        x, DQ, 0, WqTp, DQ, 0, Qp, INNER, 0, nullptr, DQ);

    // K2: Qk
    hgemm<64, 128, 2, 4, false><<<dim3(DC / 128, R_TOTAL / 64, NHEADS), 256, SM_64_128>>>(
        Qp, INNER, DHEAD, Wk, INNER, DHEAD, Qkp, NHEADS * DC, DC, nullptr, DHEAD);

    // K3: fused attention core
    attn_core<<<R_TOTAL, 256, AC_BYTES>>>(ctx, mask, bias);

    // K4: O1
    hgemm<64, 64, 2, 4, false><<<dim3(1, R_TOTAL / 64, NHEADS), 256, SM_64_64>>>(
        cAp, NHEADS * DC, DC, WvTp, DC, (long long)DHEAD * DC,
        O1p, INNER, DHEAD, nullptr, DC);

    // K5: out = O1 @ Wo + bo
    hgemm<64, 128, 2, 4, true><<<dim3(DQ / 128, R_TOTAL / 64, 1), 256, SM_64_128>>>(
        O1p, INNER, 0, WoTp, INNER, 0, out, DQ, 0, bo, INNER);
}

// round 10
// speedup vs baseline: 1.6175x; 1.2243x over previous
#include <cuda_runtime.h>
#include <cuda_fp16.h>
#include <math.h>
#include <stdint.h>

// Shapes (fixed)
#define R_TOTAL 4096
#define DQ      512
#define DC      256
#define MTOK    64
#define NHEADS  8
#define DHEAD   64
#define INNER   512

// Scratch (no allocs allowed)
__device__ float  g_Q   [R_TOTAL * INNER];
__device__ __half g_Qkh [R_TOTAL * NHEADS * DC];   // fp16 Qk (16 MB)
__device__ float  g_ctxA[R_TOTAL * NHEADS * DC];
__device__ float  g_O1  [R_TOTAL * INNER];
__device__ float  g_WqT [INNER * DQ];
__device__ float  g_WoT [DQ * INNER];
__device__ float  g_WvT [INNER * DC];

// ---------------- helpers ----------------
__device__ __forceinline__ uint32_t smem_u32(const void* p) {
    uint32_t a;
    asm("{ .reg .u64 t; cvta.to.shared.u64 t, %1; cvt.u32.u64 %0, t; }"
        : "=r"(a) : "l"(p));
    return a;
}
__device__ __forceinline__ void ldm_x4(uint32_t* r, uint32_t addr) {
    asm volatile("ldmatrix.sync.aligned.m8n8.x4.shared.b16 {%0,%1,%2,%3}, [%4];"
                 : "=r"(r[0]), "=r"(r[1]), "=r"(r[2]), "=r"(r[3]) : "r"(addr));
}
__device__ __forceinline__ void ldm_x2(uint32_t* r, uint32_t addr) {
    asm volatile("ldmatrix.sync.aligned.m8n8.x2.shared.b16 {%0,%1}, [%2];"
                 : "=r"(r[0]), "=r"(r[1]) : "r"(addr));
}
__device__ __forceinline__ void ldm_x4_t(uint32_t* r, uint32_t addr) {
    asm volatile("ldmatrix.sync.aligned.m8n8.x4.trans.shared.b16 {%0,%1,%2,%3}, [%4];"
                 : "=r"(r[0]), "=r"(r[1]), "=r"(r[2]), "=r"(r[3]) : "r"(addr));
}
__device__ __forceinline__ void ldm_x2_t(uint32_t* r, uint32_t addr) {
    asm volatile("ldmatrix.sync.aligned.m8n8.x2.trans.shared.b16 {%0,%1}, [%2];"
                 : "=r"(r[0]), "=r"(r[1]) : "r"(addr));
}
__device__ __forceinline__ void mma_f16(float* c, const uint32_t* a, const uint32_t* b) {
    asm volatile("mma.sync.aligned.m16n8k16.row.col.f32.f16.f16.f32 "
                 "{%0,%1,%2,%3}, {%4,%5,%6,%7}, {%8,%9}, {%0,%1,%2,%3};"
                 : "+f"(c[0]), "+f"(c[1]), "+f"(c[2]), "+f"(c[3])
                 : "r"(a[0]), "r"(a[1]), "r"(a[2]), "r"(a[3]), "r"(b[0]), "r"(b[1]));
}
__device__ __forceinline__ uint2 pack_h(float4 v) {
    __half2 h01 = __float22half2_rn(make_float2(v.x, v.y));
    __half2 h23 = __float22half2_rn(make_float2(v.z, v.w));
    return make_uint2(*(uint32_t*)&h01, *(uint32_t*)&h23);
}
__device__ __forceinline__ void split_h(float4 v, uint2& hi, uint2& lo) {
    __half hx = __float2half_rn(v.x);
    __half hy = __float2half_rn(v.y);
    __half hz = __float2half_rn(v.z);
    __half hw = __float2half_rn(v.w);
    __half2 h01 = __halves2half2(hx, hy);
    __half2 h23 = __halves2half2(hz, hw);
    __half2 l01 = __float22half2_rn(make_float2(v.x - __half2float(hx), v.y - __half2float(hy)));
    __half2 l23 = __float22half2_rn(make_float2(v.z - __half2float(hz), v.w - __half2float(hw)));
    hi = make_uint2(*(uint32_t*)&h01, *(uint32_t*)&h23);
    lo = make_uint2(*(uint32_t*)&l01, *(uint32_t*)&l23);
}

// ---------------------------------------------------------------------------
// fp16 2-term mma.sync GEMM: C = A·B^T (+bias). A split hi/lo, B hi.
// HOUT: write C as fp16 (for Qk).
// ---------------------------------------------------------------------------
#define LROW 40
#define LROWB 80

template<int BM, int BN, int MW, int NW, bool BIAS, bool HOUT>
__global__ __launch_bounds__(256, 2)
void hgemm(const float* __restrict__ A, int lda, long long bsA,
           const float* __restrict__ B, int ldb, long long bsB,
           void* __restrict__ Cv, int ldc, long long bsC,
           const float* __restrict__ bias, int K)
{
    constexpr int WM = BM / MW;
    constexpr int WN = BN / NW;
    constexpr int MT = WM / 16;
    constexpr int NT = WN / 8;
    constexpr int A_BYTES = BM * LROWB;
    constexpr int B_BYTES = BN * LROWB;
    constexpr int STAGE = 2 * A_BYTES + B_BYTES;

    extern __shared__ char smc[];
    const uint32_t smb = smem_u32(smc);

    const int t = threadIdx.x;
    const int wid = t >> 5, lane = t & 31;
    const int wr = wid / NW, wc = wid % NW;
    const int wm = wr * WM, wn = wc * WN;
    const int bm = blockIdx.y * BM, bn = blockIdx.x * BN;

    A += (long long)blockIdx.z * bsA;
    B += (long long)blockIdx.z * bsB;

    const int rloc = t >> 3;
    const int f4   = t & 7;

    float acc[MT][NT][4];
#pragma unroll
    for (int i = 0; i < MT; i++)
#pragma unroll
        for (int j = 0; j < NT; j++)
#pragma unroll
            for (int q = 0; q < 4; q++) acc[i][j][q] = 0.0f;

    const int ns = K >> 5;
    float4 pa[BM / 32], pb[BN / 32];

    const uint32_t a_off = (uint32_t)(((wm + (lane & 15)) * LROW + (lane >> 4) * 8) * 2);
    const uint32_t b_off = (uint32_t)(((wn + (lane & 7)) * LROW + ((lane >> 3) & 1) * 8) * 2);

    auto gload = [&](int s) {
#pragma unroll
        for (int i = 0; i < BM / 32; i++)
            pa[i] = *(const float4*)(A + (long long)(bm + rloc + i * 32) * lda + s * 32 + f4 * 4);
#pragma unroll
        for (int i = 0; i < BN / 32; i++)
            pb[i] = *(const float4*)(B + (long long)(bn + rloc + i * 32) * ldb + s * 32 + f4 * 4);
    };
    auto sstore = [&](int buf) {
        char* base = smc + buf * STAGE;
#pragma unroll
        for (int i = 0; i < BM / 32; i++) {
            uint2 hi, lo; split_h(pa[i], hi, lo);
            int r = rloc + i * 32;
            *(uint2*)(base + r * LROWB + f4 * 8)           = hi;
            *(uint2*)(base + A_BYTES + r * LROWB + f4 * 8) = lo;
        }
        char* bb = base + 2 * A_BYTES;
#pragma unroll
        for (int i = 0; i < BN / 32; i++) {
            int r = rloc + i * 32;
            *(uint2*)(bb + r * LROWB + f4 * 8) = pack_h(pb[i]);
        }
    };
    auto compute = [&](int buf) {
        const uint32_t sa = smb + buf * STAGE;
        const uint32_t sb = sa + 2 * A_BYTES;
#pragma unroll
        for (int ks = 0; ks < 2; ks++) {
            uint32_t afh[MT][4], afl[MT][4], bfh[NT][2];
#pragma unroll
            for (int mt = 0; mt < MT; mt++) {
                uint32_t ad = sa + a_off + mt * (16 * LROWB) + ks * 32;
                ldm_x4(afh[mt], ad);
                ldm_x4(afl[mt], ad + A_BYTES);
            }
#pragma unroll
            for (int nt = 0; nt < NT; nt++) {
                uint32_t bd = sb + b_off + nt * (8 * LROWB) + ks * 32;
                ldm_x2(bfh[nt], bd);
            }
#pragma unroll
            for (int mt = 0; mt < MT; mt++)
#pragma unroll
                for (int nt = 0; nt < NT; nt++) {
                    mma_f16(acc[mt][nt], afh[mt], bfh[nt]);
                    mma_f16(acc[mt][nt], afl[mt], bfh[nt]);
                }
        }
    };

    gload(0);
    sstore(0);
    __syncthreads();
    for (int s = 0; s < ns; s++) {
        if (s + 1 < ns) gload(s + 1);
        compute(s & 1);
        if (s + 1 < ns) {
            sstore((s + 1) & 1);
            __syncthreads();
        }
    }

    const int g = lane >> 2, tq = lane & 3;
    if (HOUT) {
        __half* C = (__half*)Cv + (long long)blockIdx.z * bsC;
#pragma unroll
        for (int mt = 0; mt < MT; mt++) {
            int r0 = bm + wm + mt * 16 + g;
#pragma unroll
            for (int nt = 0; nt < NT; nt++) {
                int col = bn + wn + nt * 8 + tq * 2;
                __half2 v0 = __float22half2_rn(make_float2(acc[mt][nt][0], acc[mt][nt][1]));
                __half2 v1 = __float22half2_rn(make_float2(acc[mt][nt][2], acc[mt][nt][3]));
                *(__half2*)(C + (long long)r0 * ldc + col)       = v0;
                *(__half2*)(C + (long long)(r0 + 8) * ldc + col) = v1;
            }
        }
    } else {
        float* C = (float*)Cv + (long long)blockIdx.z * bsC;
#pragma unroll
        for (int mt = 0; mt < MT; mt++) {
            int r0 = bm + wm + mt * 16 + g;
#pragma unroll
            for (int nt = 0; nt < NT; nt++) {
                int col = bn + wn + nt * 8 + tq * 2;
                float b0 = 0.f, b1 = 0.f;
                if (BIAS) { b0 = bias[col]; b1 = bias[col + 1]; }
                *(float2*)(C + (long long)r0 * ldc + col) =
                    make_float2(acc[mt][nt][0] + b0, acc[mt][nt][1] + b1);
                *(float2*)(C + (long long)(r0 + 8) * ldc + col) =
                    make_float2(acc[mt][nt][2] + b0, acc[mt][nt][3] + b1);
            }
        }
    }
}

// ---------------------------------------------------------------------------
// Weight transpose
// ---------------------------------------------------------------------------
__global__ void transpose_k(const float* __restrict__ src, float* __restrict__ dst,
                            int R, int C)
{
    __shared__ float tile[32][33];
    int bx = blockIdx.x * 32, by = blockIdx.y * 32;
#pragma unroll
    for (int j = 0; j < 32; j += 8)
        tile[threadIdx.y + j][threadIdx.x] =
            src[(long long)(by + threadIdx.y + j) * C + bx + threadIdx.x];
    __syncthreads();
#pragma unroll
    for (int j = 0; j < 32; j += 8)
        dst[(long long)(bx + threadIdx.y + j) * R + by + threadIdx.x] =
            tile[threadIdx.x][threadIdx.y + j];
}

// ---------------------------------------------------------------------------
// Tensor-core attention core, single-term fp16. One CTA per (b,l) row.
//   P1: S = ctx_hi . Qk_hi^T ; softmax ; P3: D = ctx_hi^T . attn_hi^T
// smem 46 KB -> 3-4 CTAs/SM.
// ---------------------------------------------------------------------------
#define AC_LDC 528
#define AC_CH 0          // ctx hi 64x528
#define AC_QH 33792      // qk hi 8x528
#define AC_AH 38016      // attn^T hi 64x48B
#define AC_SA 41088      // partial scores 64x9 f32
#define AC_SB 43392
#define AC_BI 45696
#define AC_MK 45952
#define AC_BYTES 46208

__global__ __launch_bounds__(256)
void attn_core(const float* __restrict__ ctx,
               const int* __restrict__ mask,
               const float* __restrict__ bias)
{
    extern __shared__ char sm[];
    const uint32_t smb = smem_u32(sm);
    const int r = blockIdx.x, t = threadIdx.x;
    const int wid = t >> 5, lane = t & 31;

    // ---- phase 0: load + fp16 pack ----
    {
        const float4* g = (const float4*)(ctx + (size_t)r * (MTOK * DC));
#pragma unroll
        for (int s = 0; s < 16; s++) {
            int i = t + s * 256;
            int m = i >> 6, c4 = i & 63;
            *(uint2*)(sm + AC_CH + m * AC_LDC + c4 * 8) = pack_h(g[i]);
        }
        // Qk already fp16: 2048 halves = 256 uint4
        {
            const uint4* gq = (const uint4*)(g_Qkh + (size_t)r * (NHEADS * DC));
            uint4 v = gq[t];
            int h = t >> 5, c16 = t & 31;
            *(uint4*)(sm + AC_QH + h * AC_LDC + c16 * 16) = v;
        }
        if (t < MTOK) {
            ((float*)(sm + AC_BI))[t] = bias[(size_t)r * MTOK + t];
            ((int*)(sm + AC_MK))[t]   = mask[(size_t)r * MTOK + t];
        }
    }
    __syncthreads();

    // ---- phase 1: scores. warp: m-tile (w&3), K-half (w>>2) ----
    {
        const int mtile = wid & 3, khalf = wid >> 2;
        float d[4] = {0.f, 0.f, 0.f, 0.f};
        const uint32_t a_base = smb + AC_CH +
            (uint32_t)((mtile * 16 + (lane & 15)) * AC_LDC + (lane >> 4) * 16);
        const uint32_t b_base = smb + AC_QH +
            (uint32_t)((lane & 7) * AC_LDC + ((lane >> 3) & 1) * 16);
#pragma unroll
        for (int j = 0; j < 8; j++) {
            const int kk = khalf * 8 + j;
            uint32_t ah[4], bh[2];
            ldm_x4(ah, a_base + kk * 32);
            ldm_x2(bh, b_base + kk * 32);
            mma_f16(d, ah, bh);
        }
        float* ss = (float*)(sm + (khalf ? AC_SB : AC_SA));
        const int gg = lane >> 2, tq = lane & 3;
        const int m0 = mtile * 16 + gg;
        ss[m0 * 9 + 2 * tq]           = d[0];
        ss[m0 * 9 + 2 * tq + 1]       = d[1];
        ss[(m0 + 8) * 9 + 2 * tq]     = d[2];
        ss[(m0 + 8) * 9 + 2 * tq + 1] = d[3];
    }
    __syncthreads();

    // ---- softmax: warp w = head h ----
    {
        const int w = wid;
        const float* sa = (const float*)(sm + AC_SA);
        const float* sb = (const float*)(sm + AC_SB);
        const float* sbias = (const float*)(sm + AC_BI);
        const int*   smask = (const int*)(sm + AC_MK);
        const int m0 = lane, m1 = lane + 32;
        float v0 = (sa[m0 * 9 + w] + sb[m0 * 9 + w]) * 0.125f + sbias[m0];
        float v1 = (sa[m1 * 9 + w] + sb[m1 * 9 + w]) * 0.125f + sbias[m1];
        if (!smask[m0]) v0 = -INFINITY;
        if (!smask[m1]) v1 = -INFINITY;
        float mx = fmaxf(v0, v1);
#pragma unroll
        for (int o = 16; o; o >>= 1) mx = fmaxf(mx, __shfl_xor_sync(0xffffffffu, mx, o));
        float e0 = __expf(v0 - mx);
        float e1 = __expf(v1 - mx);
        float s = e0 + e1;
#pragma unroll
        for (int o = 16; o; o >>= 1) s += __shfl_xor_sync(0xffffffffu, s, o);
        float inv = 1.0f / s;
        __half h0 = __float2half_rn(e0 * inv);
        __half h1 = __float2half_rn(e1 * inv);
        uint16_t* ah = (uint16_t*)(sm + AC_AH);
        ah[m0 * 24 + w] = *(uint16_t*)&h0;
        ah[m1 * 24 + w] = *(uint16_t*)&h1;
    }
    __syncthreads();

    // ---- phase 3: D[c][h] = ctx^T . attn^T ; warp w owns c-tiles 2w, 2w+1 ----
    {
        float d0[4] = {0.f, 0.f, 0.f, 0.f};
        float d1[4] = {0.f, 0.f, 0.f, 0.f};
        const int c0 = wid * 32;
        const uint32_t bt_base = smb + AC_AH +
            (uint32_t)((((lane >> 3) & 1) * 8 + (lane & 7)) * 48);
        const uint32_t at_row = (uint32_t)(((lane >> 4) & 1) * 8 + (lane & 7));
        const uint32_t at_col = (uint32_t)(((lane >> 3) & 1) * 16);
#pragma unroll
        for (int kk = 0; kk < 4; kk++) {
            uint32_t bh[2];
            ldm_x2_t(bh, bt_base + kk * 16 * 48);
            const uint32_t arow = smb + AC_CH + (kk * 16 + at_row) * AC_LDC + at_col;
            uint32_t ah0[4], ah1[4];
            ldm_x4_t(ah0, arow + c0 * 2);
            ldm_x4_t(ah1, arow + (c0 + 16) * 2);
            mma_f16(d0, ah0, bh);
            mma_f16(d1, ah1, bh);
        }
        const int gg = lane >> 2, tq = lane & 3;
        float* o = g_ctxA + (size_t)r * (NHEADS * DC);
        int c = c0 + gg;
        o[(2 * tq) * DC + c]         = d0[0];
        o[(2 * tq + 1) * DC + c]     = d0[1];
        o[(2 * tq) * DC + c + 8]     = d0[2];
        o[(2 * tq + 1) * DC + c + 8] = d0[3];
        c = c0 + 16 + gg;
        o[(2 * tq) * DC + c]         = d1[0];
        o[(2 * tq + 1) * DC + c]     = d1[1];
        o[(2 * tq) * DC + c + 8]     = d1[2];
        o[(2 * tq + 1) * DC + c + 8] = d1[3];
    }
}

// ---------------------------------------------------------------------------
extern "C" void kernel_launch(void* const* d_in, const int* in_sizes, int n_in,
                              void* d_out, int out_size)
{
    const float* x    = (const float*)d_in[0];
    const float* ctx  = (const float*)d_in[1];
    const int*   mask = (const int*)d_in[2];
    const float* bias = (const float*)d_in[3];
    const float* Wq   = (const float*)d_in[4];
    const float* Wk   = (const float*)d_in[5];
    const float* Wv   = (const float*)d_in[6];
    const float* Wo   = (const float*)d_in[7];
    const float* bo   = (const float*)d_in[8];
    float*       out  = (float*)d_out;

    float *Qp, *cAp, *O1p, *WqTp, *WoTp, *WvTp;
    __half* Qkhp;
    cudaGetSymbolAddress((void**)&Qp,   g_Q);
    cudaGetSymbolAddress((void**)&Qkhp, g_Qkh);
    cudaGetSymbolAddress((void**)&cAp,  g_ctxA);
    cudaGetSymbolAddress((void**)&O1p,  g_O1);
    cudaGetSymbolAddress((void**)&WqTp, g_WqT);
    cudaGetSymbolAddress((void**)&WoTp, g_WoT);
    cudaGetSymbolAddress((void**)&WvTp, g_WvT);

    const int SM_64_128 = 2 * (2 * 64 * LROWB + 128 * LROWB);   // 40960
    const int SM_64_64  = 2 * (2 * 64 * LROWB + 64 * LROWB);    // 30720
    cudaFuncSetAttribute((const void*)hgemm<64, 128, 2, 4, false, false>,
                         cudaFuncAttributeMaxDynamicSharedMemorySize, SM_64_128);
    cudaFuncSetAttribute((const void*)hgemm<64, 128, 2, 4, true, false>,
                         cudaFuncAttributeMaxDynamicSharedMemorySize, SM_64_128);
    cudaFuncSetAttribute((const void*)hgemm<64, 128, 2, 4, false, true>,
                         cudaFuncAttributeMaxDynamicSharedMemorySize, SM_64_128);
    cudaFuncSetAttribute((const void*)hgemm<64, 64, 2, 4, false, false>,
                         cudaFuncAttributeMaxDynamicSharedMemorySize, SM_64_64);
    cudaFuncSetAttribute((const void*)attn_core,
                         cudaFuncAttributeMaxDynamicSharedMemorySize, AC_BYTES);

    dim3 tb(32, 8);
    transpose_k<<<dim3(16, 16), tb>>>(Wq, WqTp, DQ, INNER);
    transpose_k<<<dim3(16, 16), tb>>>(Wo, WoTp, INNER, DQ);
    transpose_k<<<dim3(16, 8),  tb>>>(Wv, WvTp, DC, INNER);

    // K1: Q = x @ Wq
    hgemm<64, 128, 2, 4, false, false><<<dim3(INNER / 128, R_TOTAL / 64, 1), 256, SM_64_128>>>(
        x, DQ, 0, WqTp, DQ, 0, Qp, INNER, 0, nullptr, DQ);

    // K2: Qk (fp16 output)
    hgemm<64, 128, 2, 4, false, true><<<dim3(DC / 128, R_TOTAL / 64, NHEADS), 256, SM_64_128>>>(
        Qp, INNER, DHEAD, Wk, INNER, DHEAD, Qkhp, NHEADS * DC, DC, nullptr, DHEAD);

    // K3: fused attention core (single-term fp16)
    attn_core<<<R_TOTAL, 256, AC_BYTES>>>(ctx, mask, bias);

    // K4: O1
    hgemm<64, 64, 2, 4, false, false><<<dim3(1, R_TOTAL / 64, NHEADS), 256, SM_64_64>>>(
        cAp, NHEADS * DC, DC, WvTp, DC, (long long)DHEAD * DC,
        O1p, INNER, DHEAD, nullptr, DC);

    // K5: out = O1 @ Wo + bo
    hgemm<64, 128, 2, 4, true, false><<<dim3(DQ / 128, R_TOTAL / 64, 1), 256, SM_64_128>>>(
        O1p, INNER, 0, WoTp, INNER, 0, out, DQ, 0, bo, INNER);
}

// round 11
// speedup vs baseline: 1.8253x; 1.1284x over previous
#include <cuda_runtime.h>
#include <cuda_fp16.h>
#include <math.h>
#include <stdint.h>

// Shapes (fixed)
#define R_TOTAL 4096
#define DQ      512
#define DC      256
#define MTOK    64
#define NHEADS  8
#define DHEAD   64
#define INNER   512

// Scratch (no allocs allowed) — fp16 intermediates
__device__ __half g_Qh  [R_TOTAL * INNER];          // 4 MB
__device__ __half g_Qkh [R_TOTAL * NHEADS * DC];    // 16 MB
__device__ __half g_ctxAh[R_TOTAL * NHEADS * DC];   // 16 MB
__device__ __half g_O1h [R_TOTAL * INNER];          // 4 MB
__device__ float  g_WqT [INNER * DQ];
__device__ float  g_WoT [DQ * INNER];
__device__ float  g_WvT [INNER * DC];

// ---------------- helpers ----------------
__device__ __forceinline__ uint32_t smem_u32(const void* p) {
    uint32_t a;
    asm("{ .reg .u64 t; cvta.to.shared.u64 t, %1; cvt.u32.u64 %0, t; }"
        : "=r"(a) : "l"(p));
    return a;
}
__device__ __forceinline__ void ldm_x4(uint32_t* r, uint32_t addr) {
    asm volatile("ldmatrix.sync.aligned.m8n8.x4.shared.b16 {%0,%1,%2,%3}, [%4];"
                 : "=r"(r[0]), "=r"(r[1]), "=r"(r[2]), "=r"(r[3]) : "r"(addr));
}
__device__ __forceinline__ void ldm_x2(uint32_t* r, uint32_t addr) {
    asm volatile("ldmatrix.sync.aligned.m8n8.x2.shared.b16 {%0,%1}, [%2];"
                 : "=r"(r[0]), "=r"(r[1]) : "r"(addr));
}
__device__ __forceinline__ void ldm_x4_t(uint32_t* r, uint32_t addr) {
    asm volatile("ldmatrix.sync.aligned.m8n8.x4.trans.shared.b16 {%0,%1,%2,%3}, [%4];"
                 : "=r"(r[0]), "=r"(r[1]), "=r"(r[2]), "=r"(r[3]) : "r"(addr));
}
__device__ __forceinline__ void ldm_x2_t(uint32_t* r, uint32_t addr) {
    asm volatile("ldmatrix.sync.aligned.m8n8.x2.trans.shared.b16 {%0,%1}, [%2];"
                 : "=r"(r[0]), "=r"(r[1]) : "r"(addr));
}
__device__ __forceinline__ void mma_f16(float* c, const uint32_t* a, const uint32_t* b) {
    asm volatile("mma.sync.aligned.m16n8k16.row.col.f32.f16.f16.f32 "
                 "{%0,%1,%2,%3}, {%4,%5,%6,%7}, {%8,%9}, {%0,%1,%2,%3};"
                 : "+f"(c[0]), "+f"(c[1]), "+f"(c[2]), "+f"(c[3])
                 : "r"(a[0]), "r"(a[1]), "r"(a[2]), "r"(a[3]), "r"(b[0]), "r"(b[1]));
}
__device__ __forceinline__ uint2 pack_h(float4 v) {
    __half2 h01 = __float22half2_rn(make_float2(v.x, v.y));
    __half2 h23 = __float22half2_rn(make_float2(v.z, v.w));
    return make_uint2(*(uint32_t*)&h01, *(uint32_t*)&h23);
}

// ---------------------------------------------------------------------------
// fp16 single-term mma.sync GEMM: C = A·B^T (+bias).
// AHALF: A already fp16 in gmem (direct copy); else fp32 -> hi pack.
// HOUT: write C as fp16.
// ---------------------------------------------------------------------------
#define LROW 40
#define LROWB 80

template<int BM, int BN, int MW, int NW, bool BIAS, bool HOUT, bool AHALF>
__global__ __launch_bounds__(256, 2)
void hgemm(const void* __restrict__ Av, int lda, long long bsA,
           const float* __restrict__ B, int ldb, long long bsB,
           void* __restrict__ Cv, int ldc, long long bsC,
           const float* __restrict__ bias, int K)
{
    constexpr int WM = BM / MW;
    constexpr int WN = BN / NW;
    constexpr int MT = WM / 16;
    constexpr int NT = WN / 8;
    constexpr int A_BYTES = BM * LROWB;
    constexpr int B_BYTES = BN * LROWB;
    constexpr int STAGE = A_BYTES + B_BYTES;

    extern __shared__ char smc[];
    const uint32_t smb = smem_u32(smc);

    const int t = threadIdx.x;
    const int wid = t >> 5, lane = t & 31;
    const int wr = wid / NW, wc = wid % NW;
    const int wm = wr * WM, wn = wc * WN;
    const int bm = blockIdx.y * BM, bn = blockIdx.x * BN;

    const float*  Af = AHALF ? nullptr : ((const float*)Av + (long long)blockIdx.z * bsA);
    const __half* Ah = AHALF ? ((const __half*)Av + (long long)blockIdx.z * bsA) : nullptr;
    B += (long long)blockIdx.z * bsB;

    const int rloc = t >> 3;
    const int f4   = t & 7;

    float acc[MT][NT][4];
#pragma unroll
    for (int i = 0; i < MT; i++)
#pragma unroll
        for (int j = 0; j < NT; j++)
#pragma unroll
            for (int q = 0; q < 4; q++) acc[i][j][q] = 0.0f;

    const int ns = K >> 5;
    float4 pa[BM / 32], pb[BN / 32];
    uint2  pah[BM / 32];

    const uint32_t a_off = (uint32_t)(((wm + (lane & 15)) * LROW + (lane >> 4) * 8) * 2);
    const uint32_t b_off = (uint32_t)(((wn + (lane & 7)) * LROW + ((lane >> 3) & 1) * 8) * 2);

    auto gload = [&](int s) {
#pragma unroll
        for (int i = 0; i < BM / 32; i++) {
            if (AHALF)
                pah[i] = *(const uint2*)(Ah + (long long)(bm + rloc + i * 32) * lda + s * 32 + f4 * 4);
            else
                pa[i] = *(const float4*)(Af + (long long)(bm + rloc + i * 32) * lda + s * 32 + f4 * 4);
        }
#pragma unroll
        for (int i = 0; i < BN / 32; i++)
            pb[i] = *(const float4*)(B + (long long)(bn + rloc + i * 32) * ldb + s * 32 + f4 * 4);
    };
    auto sstore = [&](int buf) {
        char* base = smc + buf * STAGE;
#pragma unroll
        for (int i = 0; i < BM / 32; i++) {
            int r = rloc + i * 32;
            uint2 hv = AHALF ? pah[i] : pack_h(pa[i]);
            *(uint2*)(base + r * LROWB + f4 * 8) = hv;
        }
        char* bb = base + A_BYTES;
#pragma unroll
        for (int i = 0; i < BN / 32; i++) {
            int r = rloc + i * 32;
            *(uint2*)(bb + r * LROWB + f4 * 8) = pack_h(pb[i]);
        }
    };
    auto compute = [&](int buf) {
        const uint32_t sa = smb + buf * STAGE;
        const uint32_t sb = sa + A_BYTES;
#pragma unroll
        for (int ks = 0; ks < 2; ks++) {
            uint32_t afh[MT][4], bfh[NT][2];
#pragma unroll
            for (int mt = 0; mt < MT; mt++)
                ldm_x4(afh[mt], sa + a_off + mt * (16 * LROWB) + ks * 32);
#pragma unroll
            for (int nt = 0; nt < NT; nt++)
                ldm_x2(bfh[nt], sb + b_off + nt * (8 * LROWB) + ks * 32);
#pragma unroll
            for (int mt = 0; mt < MT; mt++)
#pragma unroll
                for (int nt = 0; nt < NT; nt++)
                    mma_f16(acc[mt][nt], afh[mt], bfh[nt]);
        }
    };

    gload(0);
    sstore(0);
    __syncthreads();
    for (int s = 0; s < ns; s++) {
        if (s + 1 < ns) gload(s + 1);
        compute(s & 1);
        if (s + 1 < ns) {
            sstore((s + 1) & 1);
            __syncthreads();
        }
    }

    const int g = lane >> 2, tq = lane & 3;
    if (HOUT) {
        __half* C = (__half*)Cv + (long long)blockIdx.z * bsC;
#pragma unroll
        for (int mt = 0; mt < MT; mt++) {
            int r0 = bm + wm + mt * 16 + g;
#pragma unroll
            for (int nt = 0; nt < NT; nt++) {
                int col = bn + wn + nt * 8 + tq * 2;
                __half2 v0 = __float22half2_rn(make_float2(acc[mt][nt][0], acc[mt][nt][1]));
                __half2 v1 = __float22half2_rn(make_float2(acc[mt][nt][2], acc[mt][nt][3]));
                *(__half2*)(C + (long long)r0 * ldc + col)       = v0;
                *(__half2*)(C + (long long)(r0 + 8) * ldc + col) = v1;
            }
        }
    } else {
        float* C = (float*)Cv + (long long)blockIdx.z * bsC;
#pragma unroll
        for (int mt = 0; mt < MT; mt++) {
            int r0 = bm + wm + mt * 16 + g;
#pragma unroll
            for (int nt = 0; nt < NT; nt++) {
                int col = bn + wn + nt * 8 + tq * 2;
                float b0 = 0.f, b1 = 0.f;
                if (BIAS) { b0 = bias[col]; b1 = bias[col + 1]; }
                *(float2*)(C + (long long)r0 * ldc + col) =
                    make_float2(acc[mt][nt][0] + b0, acc[mt][nt][1] + b1);
                *(float2*)(C + (long long)(r0 + 8) * ldc + col) =
                    make_float2(acc[mt][nt][2] + b0, acc[mt][nt][3] + b1);
            }
        }
    }
}

// ---------------------------------------------------------------------------
// Weight transpose
// ---------------------------------------------------------------------------
__global__ void transpose_k(const float* __restrict__ src, float* __restrict__ dst,
                            int R, int C)
{
    __shared__ float tile[32][33];
    int bx = blockIdx.x * 32, by = blockIdx.y * 32;
#pragma unroll
    for (int j = 0; j < 32; j += 8)
        tile[threadIdx.y + j][threadIdx.x] =
            src[(long long)(by + threadIdx.y + j) * C + bx + threadIdx.x];
    __syncthreads();
#pragma unroll
    for (int j = 0; j < 32; j += 8)
        dst[(long long)(bx + threadIdx.y + j) * R + by + threadIdx.x] =
            tile[threadIdx.x][threadIdx.y + j];
}

// ---------------------------------------------------------------------------
// Tensor-core attention core, single-term fp16. One CTA per (b,l) row.
// Output ctxA written as fp16 (feeds K4's AHALF path).
// ---------------------------------------------------------------------------
#define AC_LDC 528
#define AC_CH 0
#define AC_QH 33792
#define AC_AH 38016
#define AC_SA 41088
#define AC_SB 43392
#define AC_BI 45696
#define AC_MK 45952
#define AC_BYTES 46208

__global__ __launch_bounds__(256)
void attn_core(const float* __restrict__ ctx,
               const int* __restrict__ mask,
               const float* __restrict__ bias)
{
    extern __shared__ char sm[];
    const uint32_t smb = smem_u32(sm);
    const int r = blockIdx.x, t = threadIdx.x;
    const int wid = t >> 5, lane = t & 31;

    // ---- phase 0: load + fp16 pack ----
    {
        const float4* g = (const float4*)(ctx + (size_t)r * (MTOK * DC));
#pragma unroll
        for (int s = 0; s < 16; s++) {
            int i = t + s * 256;
            int m = i >> 6, c4 = i & 63;
            *(uint2*)(sm + AC_CH + m * AC_LDC + c4 * 8) = pack_h(g[i]);
        }
        {
            const uint4* gq = (const uint4*)(g_Qkh + (size_t)r * (NHEADS * DC));
            uint4 v = gq[t];
            int h = t >> 5, c16 = t & 31;
            *(uint4*)(sm + AC_QH + h * AC_LDC + c16 * 16) = v;
        }
        if (t < MTOK) {
            ((float*)(sm + AC_BI))[t] = bias[(size_t)r * MTOK + t];
            ((int*)(sm + AC_MK))[t]   = mask[(size_t)r * MTOK + t];
        }
    }
    __syncthreads();

    // ---- phase 1: scores ----
    {
        const int mtile = wid & 3, khalf = wid >> 2;
        float d[4] = {0.f, 0.f, 0.f, 0.f};
        const uint32_t a_base = smb + AC_CH +
            (uint32_t)((mtile * 16 + (lane & 15)) * AC_LDC + (lane >> 4) * 16);
        const uint32_t b_base = smb + AC_QH +
            (uint32_t)((lane & 7) * AC_LDC + ((lane >> 3) & 1) * 16);
#pragma unroll
        for (int j = 0; j < 8; j++) {
            const int kk = khalf * 8 + j;
            uint32_t ah[4], bh[2];
            ldm_x4(ah, a_base + kk * 32);
            ldm_x2(bh, b_base + kk * 32);
            mma_f16(d, ah, bh);
        }
        float* ss = (float*)(sm + (khalf ? AC_SB : AC_SA));
        const int gg = lane >> 2, tq = lane & 3;
        const int m0 = mtile * 16 + gg;
        ss[m0 * 9 + 2 * tq]           = d[0];
        ss[m0 * 9 + 2 * tq + 1]       = d[1];
        ss[(m0 + 8) * 9 + 2 * tq]     = d[2];
        ss[(m0 + 8) * 9 + 2 * tq + 1] = d[3];
    }
    __syncthreads();

    // ---- softmax ----
    {
        const int w = wid;
        const float* sa = (const float*)(sm + AC_SA);
        const float* sb = (const float*)(sm + AC_SB);
        const float* sbias = (const float*)(sm + AC_BI);
        const int*   smask = (const int*)(sm + AC_MK);
        const int m0 = lane, m1 = lane + 32;
        float v0 = (sa[m0 * 9 + w] + sb[m0 * 9 + w]) * 0.125f + sbias[m0];
        float v1 = (sa[m1 * 9 + w] + sb[m1 * 9 + w]) * 0.125f + sbias[m1];
        if (!smask[m0]) v0 = -INFINITY;
        if (!smask[m1]) v1 = -INFINITY;
        float mx = fmaxf(v0, v1);
#pragma unroll
        for (int o = 16; o; o >>= 1) mx = fmaxf(mx, __shfl_xor_sync(0xffffffffu, mx, o));
        float e0 = __expf(v0 - mx);
        float e1 = __expf(v1 - mx);
        float s = e0 + e1;
#pragma unroll
        for (int o = 16; o; o >>= 1) s += __shfl_xor_sync(0xffffffffu, s, o);
        float inv = 1.0f / s;
        __half h0 = __float2half_rn(e0 * inv);
        __half h1 = __float2half_rn(e1 * inv);
        uint16_t* ah = (uint16_t*)(sm + AC_AH);
        ah[m0 * 24 + w] = *(uint16_t*)&h0;
        ah[m1 * 24 + w] = *(uint16_t*)&h1;
    }
    __syncthreads();

    // ---- phase 3: D[c][h] -> fp16 ctxA ----
    {
        float d0[4] = {0.f, 0.f, 0.f, 0.f};
        float d1[4] = {0.f, 0.f, 0.f, 0.f};
        const int c0 = wid * 32;
        const uint32_t bt_base = smb + AC_AH +
            (uint32_t)((((lane >> 3) & 1) * 8 + (lane & 7)) * 48);
        const uint32_t at_row = (uint32_t)(((lane >> 4) & 1) * 8 + (lane & 7));
        const uint32_t at_col = (uint32_t)(((lane >> 3) & 1) * 16);
#pragma unroll
        for (int kk = 0; kk < 4; kk++) {
            uint32_t bh[2];
            ldm_x2_t(bh, bt_base + kk * 16 * 48);
            const uint32_t arow = smb + AC_CH + (kk * 16 + at_row) * AC_LDC + at_col;
            uint32_t ah0[4], ah1[4];
            ldm_x4_t(ah0, arow + c0 * 2);
            ldm_x4_t(ah1, arow + (c0 + 16) * 2);
            mma_f16(d0, ah0, bh);
            mma_f16(d1, ah1, bh);
        }
        const int gg = lane >> 2, tq = lane & 3;
        __half* o = g_ctxAh + (size_t)r * (NHEADS * DC);
        int c = c0 + gg;
        o[(2 * tq) * DC + c]         = __float2half_rn(d0[0]);
        o[(2 * tq + 1) * DC + c]     = __float2half_rn(d0[1]);
        o[(2 * tq) * DC + c + 8]     = __float2half_rn(d0[2]);
        o[(2 * tq + 1) * DC + c + 8] = __float2half_rn(d0[3]);
        c = c0 + 16 + gg;
        o[(2 * tq) * DC + c]         = __float2half_rn(d1[0]);
        o[(2 * tq + 1) * DC + c]     = __float2half_rn(d1[1]);
        o[(2 * tq) * DC + c + 8]     = __float2half_rn(d1[2]);
        o[(2 * tq + 1) * DC + c + 8] = __float2half_rn(d1[3]);
    }
}

// ---------------------------------------------------------------------------
extern "C" void kernel_launch(void* const* d_in, const int* in_sizes, int n_in,
                              void* d_out, int out_size)
{
    const float* x    = (const float*)d_in[0];
    const float* ctx  = (const float*)d_in[1];
    const int*   mask = (const int*)d_in[2];
    const float* bias = (const float*)d_in[3];
    const float* Wq   = (const float*)d_in[4];
    const float* Wk   = (const float*)d_in[5];
    const float* Wv   = (const float*)d_in[6];
    const float* Wo   = (const float*)d_in[7];
    const float* bo   = (const float*)d_in[8];
    float*       out  = (float*)d_out;

    float *WqTp, *WoTp, *WvTp;
    __half *Qhp, *Qkhp, *cAhp, *O1hp;
    cudaGetSymbolAddress((void**)&Qhp,  g_Qh);
    cudaGetSymbolAddress((void**)&Qkhp, g_Qkh);
    cudaGetSymbolAddress((void**)&cAhp, g_ctxAh);
    cudaGetSymbolAddress((void**)&O1hp, g_O1h);
    cudaGetSymbolAddress((void**)&WqTp, g_WqT);
    cudaGetSymbolAddress((void**)&WoTp, g_WoT);
    cudaGetSymbolAddress((void**)&WvTp, g_WvT);

    // smem: 2 stages * (BM*80 + BN*80)
    const int SM_64_128 = 2 * (64 * LROWB + 128 * LROWB);   // 30720
    const int SM_64_64  = 2 * (64 * LROWB + 64 * LROWB);    // 20480
    cudaFuncSetAttribute((const void*)hgemm<64, 128, 2, 4, false, true,  false>,
                         cudaFuncAttributeMaxDynamicSharedMemorySize, SM_64_128);
    cudaFuncSetAttribute((const void*)hgemm<64, 128, 2, 4, false, true,  true>,
                         cudaFuncAttributeMaxDynamicSharedMemorySize, SM_64_128);
    cudaFuncSetAttribute((const void*)hgemm<64, 128, 2, 4, true,  false, true>,
                         cudaFuncAttributeMaxDynamicSharedMemorySize, SM_64_128);
    cudaFuncSetAttribute((const void*)hgemm<64, 64, 2, 4, false, true, true>,
                         cudaFuncAttributeMaxDynamicSharedMemorySize, SM_64_64);
    cudaFuncSetAttribute((const void*)attn_core,
                         cudaFuncAttributeMaxDynamicSharedMemorySize, AC_BYTES);

    dim3 tb(32, 8);
    transpose_k<<<dim3(16, 16), tb>>>(Wq, WqTp, DQ, INNER);
    transpose_k<<<dim3(16, 16), tb>>>(Wo, WoTp, INNER, DQ);
    transpose_k<<<dim3(16, 8),  tb>>>(Wv, WvTp, DC, INNER);

    // K1: Q = x @ Wq  -> fp16 Q
    hgemm<64, 128, 2, 4, false, true, false><<<dim3(INNER / 128, R_TOTAL / 64, 1), 256, SM_64_128>>>(
        x, DQ, 0, WqTp, DQ, 0, Qhp, INNER, 0, nullptr, DQ);

    // K2: Qk = Q_h @ Wk^T (per head) -> fp16 Qk
    hgemm<64, 128, 2, 4, false, true, true><<<dim3(DC / 128, R_TOTAL / 64, NHEADS), 256, SM_64_128>>>(
        Qhp, INNER, DHEAD, Wk, INNER, DHEAD, Qkhp, NHEADS * DC, DC, nullptr, DHEAD);

    // K3: fused attention core -> fp16 ctxA
    attn_core<<<R_TOTAL, 256, AC_BYTES>>>(ctx, mask, bias);

    // K4: O1 = ctxA_h @ WvT^T (per head) -> fp16 O1
    hgemm<64, 64, 2, 4, false, true, true><<<dim3(1, R_TOTAL / 64, NHEADS), 256, SM_64_64>>>(
        cAhp, NHEADS * DC, DC, WvTp, DC, (long long)DHEAD * DC,
        O1hp, INNER, DHEAD, nullptr, DC);

    // K5: out = O1_h @ Wo + bo  (fp32 out)
    hgemm<64, 128, 2, 4, true, false, true><<<dim3(DQ / 128, R_TOTAL / 64, 1), 256, SM_64_128>>>(
        O1hp, INNER, 0, WoTp, INNER, 0, out, DQ, 0, bo, INNER);
}